// round 5
// baseline (speedup 1.0000x reference)
#include <cuda_runtime.h>
#include <math.h>
#include <stdint.h>

#define NB 4
#define SEQ 128
#define DL 128
#define DM 16
#define SO 120
#define ROWS (NB*SEQ)        // 512

typedef unsigned long long u64;

// packed fp32x2 FMA (sm_100+): d = a*b + c on both 32-bit halves
#define FMA2(d,a,b,c) asm("fma.rn.f32x2 %0, %1, %2, %3;" : "=l"(d) : "l"(a), "l"(b), "l"(c))
#define DUP2(d,s)     asm("mov.b64 %0, {%1, %1};" : "=l"(d) : "r"(__float_as_uint(s)))
#define UNPK2(lo,hi,p) asm("mov.b64 {%0, %1}, %2;" : "=r"(lo), "=r"(hi) : "l"(p))
#define LDS_2x64(p0,p1,addr) asm volatile("ld.shared.v2.b64 {%0, %1}, [%2];" : "=l"(p0), "=l"(p1) : "r"(addr))

// ---------------- scratch (device globals; no allocations allowed) ----------
__device__ float g_Q[ROWS*DL];
__device__ float g_K[ROWS*DL];
__device__ float g_U[ROWS*256];
__device__ float g_attn[NB*SEQ*SEQ];
__device__ float g_lie[(size_t)NB*SEQ*SEQ*SO];   // 31.5 MB
__device__ float g_settled[ROWS*DM];

__constant__ int c_tri_r[120] = {
 0,0,0,0,0,0,0,0,0,0,0,0,0,0,0,
 1,1,1,1,1,1,1,1,1,1,1,1,1,1,
 2,2,2,2,2,2,2,2,2,2,2,2,2,
 3,3,3,3,3,3,3,3,3,3,3,3,
 4,4,4,4,4,4,4,4,4,4,4,
 5,5,5,5,5,5,5,5,5,5,
 6,6,6,6,6,6,6,6,6,
 7,7,7,7,7,7,7,7,
 8,8,8,8,8,8,8,
 9,9,9,9,9,9,
 10,10,10,10,10,
 11,11,11,11,
 12,12,12,
 13,13,
 14};
__constant__ int c_tri_c[120] = {
 1,2,3,4,5,6,7,8,9,10,11,12,13,14,15,
 2,3,4,5,6,7,8,9,10,11,12,13,14,15,
 3,4,5,6,7,8,9,10,11,12,13,14,15,
 4,5,6,7,8,9,10,11,12,13,14,15,
 5,6,7,8,9,10,11,12,13,14,15,
 6,7,8,9,10,11,12,13,14,15,
 7,8,9,10,11,12,13,14,15,
 8,9,10,11,12,13,14,15,
 9,10,11,12,13,14,15,
 10,11,12,13,14,15,
 11,12,13,14,15,
 12,13,14,15,
 13,14,15,
 14,15,
 15};

__device__ __forceinline__ float ftanh(float x) {
    float y;
    asm("tanh.approx.f32 %0, %1;" : "=f"(y) : "f"(x));
    return y;
}

// ---------------- kernel A: tiled GEMM  C[512 x 512] = X @ [Wq;Wk;W1]^T ----
__global__ void __launch_bounds__(256)
prep_kernel(const float* __restrict__ xl,
            const float* __restrict__ Wq, const float* __restrict__ bq,
            const float* __restrict__ Wk, const float* __restrict__ bk,
            const float* __restrict__ W1)
{
    __shared__ __align__(16) float Xs[64*64];
    __shared__ __align__(16) float Wt[64*68];

    int bx = blockIdx.x, by = blockIdx.y;
    int t  = threadIdx.x;
    int tx = t & 15, ty = t >> 4;

    const float* src;
    if      (by < 2) src = Wq + (by    )*64*DL;
    else if (by < 4) src = Wk + (by - 2)*64*DL;
    else             src = W1 + (by - 4)*64*DL;

    float acc[4][4];
    #pragma unroll
    for (int i = 0; i < 4; i++)
        #pragma unroll
        for (int j = 0; j < 4; j++) acc[i][j] = 0.f;

    for (int k0 = 0; k0 < DL; k0 += 64) {
        __syncthreads();
        #pragma unroll
        for (int s = 0; s < 16; s++) {
            int idx = t + 256*s;
            int r = idx >> 6, k = idx & 63;
            Xs[r*64 + k] = xl[(bx*64 + r)*DL + k0 + k];
            Wt[k*68 + r] = src[r*DL + k0 + k];
        }
        __syncthreads();

        #pragma unroll 8
        for (int k = 0; k < 64; k++) {
            float4 bv = *(const float4*)&Wt[k*68 + tx*4];
            #pragma unroll
            for (int i = 0; i < 4; i++) {
                float a = Xs[(ty*4 + i)*64 + k];
                acc[i][0] = fmaf(a, bv.x, acc[i][0]);
                acc[i][1] = fmaf(a, bv.y, acc[i][1]);
                acc[i][2] = fmaf(a, bv.z, acc[i][2]);
                acc[i][3] = fmaf(a, bv.w, acc[i][3]);
            }
        }
    }

    #pragma unroll
    for (int i = 0; i < 4; i++) {
        int rowg = bx*64 + ty*4 + i;
        int c0   = tx*4;
        if (by < 2) {
            int col = by*64 + c0;
            *(float4*)&g_Q[rowg*DL + col] =
                make_float4(acc[i][0]+bq[col], acc[i][1]+bq[col+1],
                            acc[i][2]+bq[col+2], acc[i][3]+bq[col+3]);
        } else if (by < 4) {
            int col = (by-2)*64 + c0;
            *(float4*)&g_K[rowg*DL + col] =
                make_float4(acc[i][0]+bk[col], acc[i][1]+bk[col+1],
                            acc[i][2]+bk[col+2], acc[i][3]+bk[col+3]);
        } else {
            int col = (by-4)*64 + c0;
            *(float4*)&g_U[rowg*256 + col] =
                make_float4(acc[i][0], acc[i][1], acc[i][2], acc[i][3]);
        }
    }
}

// ---------------- kernel B: attention softmax (+ zero g_settled) -----------
#define AT_QS 0
#define AT_KT (AT_QS + 32*128)
#define AT_S  (AT_KT + 128*132)
#define AT_FLOATS (AT_S + 32*132)
#define AT_BYTES  (AT_FLOATS*4)

__global__ void __launch_bounds__(256)
attn_kernel()
{
    extern __shared__ float sm[];
    float* Qs = sm + AT_QS;
    float* Kt = sm + AT_KT;
    float* S  = sm + AT_S;

    int b  = blockIdx.x >> 2;
    int jt = (blockIdx.x & 3) * 32;
    int t  = threadIdx.x;
    int tx = t & 15, ty = t >> 4;

    for (int z = t; z < 512; z += 256) g_settled[blockIdx.x*512 + z] = 0.f;

    for (int idx = t; idx < 32*128; idx += 256) {
        int j = idx >> 7, k = idx & 127;
        Qs[j*128 + k] = g_Q[(b*SEQ + jt + j)*DL + k];
    }
    for (int idx = t; idx < 128*128; idx += 256) {
        int i = idx >> 7, k = idx & 127;
        Kt[k*132 + i] = g_K[(b*SEQ + i)*DL + k];
    }
    __syncthreads();

    float acc[2][8];
    #pragma unroll
    for (int i = 0; i < 2; i++)
        #pragma unroll
        for (int j = 0; j < 8; j++) acc[i][j] = 0.f;

    int j0 = ty*2, i0 = tx*8;
    #pragma unroll 4
    for (int k = 0; k < 128; k++) {
        float q0 = Qs[(j0  )*128 + k];
        float q1 = Qs[(j0+1)*128 + k];
        float4 k0v = *(const float4*)&Kt[k*132 + i0];
        float4 k1v = *(const float4*)&Kt[k*132 + i0 + 4];
        acc[0][0]=fmaf(q0,k0v.x,acc[0][0]); acc[0][1]=fmaf(q0,k0v.y,acc[0][1]);
        acc[0][2]=fmaf(q0,k0v.z,acc[0][2]); acc[0][3]=fmaf(q0,k0v.w,acc[0][3]);
        acc[0][4]=fmaf(q0,k1v.x,acc[0][4]); acc[0][5]=fmaf(q0,k1v.y,acc[0][5]);
        acc[0][6]=fmaf(q0,k1v.z,acc[0][6]); acc[0][7]=fmaf(q0,k1v.w,acc[0][7]);
        acc[1][0]=fmaf(q1,k0v.x,acc[1][0]); acc[1][1]=fmaf(q1,k0v.y,acc[1][1]);
        acc[1][2]=fmaf(q1,k0v.z,acc[1][2]); acc[1][3]=fmaf(q1,k0v.w,acc[1][3]);
        acc[1][4]=fmaf(q1,k1v.x,acc[1][4]); acc[1][5]=fmaf(q1,k1v.y,acc[1][5]);
        acc[1][6]=fmaf(q1,k1v.z,acc[1][6]); acc[1][7]=fmaf(q1,k1v.w,acc[1][7]);
    }
    const float sc = 0.08838834764831845f;
    #pragma unroll
    for (int i = 0; i < 2; i++) {
        *(float4*)&S[(j0+i)*132 + i0] =
            make_float4(acc[i][0]*sc, acc[i][1]*sc, acc[i][2]*sc, acc[i][3]*sc);
        *(float4*)&S[(j0+i)*132 + i0 + 4] =
            make_float4(acc[i][4]*sc, acc[i][5]*sc, acc[i][6]*sc, acc[i][7]*sc);
    }
    __syncthreads();

    int w = t >> 5, lane = t & 31;
    for (int q = 0; q < 4; q++) {
        int r = w*4 + q;
        float v0 = S[r*132 + lane      ];
        float v1 = S[r*132 + lane + 32 ];
        float v2 = S[r*132 + lane + 64 ];
        float v3 = S[r*132 + lane + 96 ];
        float mx = fmaxf(fmaxf(v0,v1), fmaxf(v2,v3));
        #pragma unroll
        for (int off = 16; off; off >>= 1)
            mx = fmaxf(mx, __shfl_xor_sync(0xffffffffu, mx, off));
        float e0 = expf(v0-mx), e1 = expf(v1-mx), e2 = expf(v2-mx), e3 = expf(v3-mx);
        float sum = e0+e1+e2+e3;
        #pragma unroll
        for (int off = 16; off; off >>= 1)
            sum += __shfl_xor_sync(0xffffffffu, sum, off);
        float inv = 1.f/sum;
        float* dst = g_attn + (b*SEQ + jt + r)*SEQ;
        dst[lane     ] = e0*inv;
        dst[lane + 32] = e1*inv;
        dst[lane + 64] = e2*inv;
        dst[lane + 96] = e3*inv;
    }
}

// ---------------- kernel C: pairwise MLP GEMM -> g_lie  (FFMA2) ------------
__global__ void __launch_bounds__(256, 2)
pair_kernel(const float* __restrict__ b1, const float* __restrict__ W2,
            const float* __restrict__ b2)
{
    __shared__ __align__(16) float Ujb[256];
    __shared__ __align__(16) float As[32*132];   // [kk][i]
    __shared__ __align__(16) float Bs[32*132];   // [kk][c]

    int row = blockIdx.x;          // b*128 + j
    int b   = row >> 7;
    int t   = threadIdx.x;

    Ujb[t] = g_U[row*256 + t] + b1[t];

    int i0 = (t & 15) * 8;
    int c0 = (t >> 4) * 8;

    unsigned asBase = (unsigned)__cvta_generic_to_shared(As) + i0*4;
    unsigned bsBase = (unsigned)__cvta_generic_to_shared(Bs) + c0*4;

    u64 acc2[8][4];
    #pragma unroll
    for (int i = 0; i < 8; i++)
        #pragma unroll
        for (int j = 0; j < 4; j++) acc2[i][j] = 0ull;

    for (int k0 = 0; k0 < 256; k0 += 32) {
        __syncthreads();
        #pragma unroll
        for (int s = 0; s < 16; s++) {
            int idx = t + 256*s;          // 4096
            int i = idx >> 5, kk = idx & 31;
            float u = g_U[(b*SEQ + i)*256 + k0 + kk];
            As[kk*132 + i] = ftanh(Ujb[k0 + kk] - u);
        }
        #pragma unroll
        for (int s = 0; s < 15; s++) {
            int idx = t + 256*s;          // 3840
            int c = idx >> 5, kk = idx & 31;
            Bs[kk*132 + c] = W2[c*256 + k0 + kk];
        }
        { int c = 120 + (t >> 5), kk = t & 31; Bs[kk*132 + c] = 0.f; }
        __syncthreads();

        #pragma unroll
        for (int kk = 0; kk < 32; kk++) {
            unsigned aAddr = asBase + kk*132*4;
            unsigned bAddr = bsBase + kk*132*4;
            float4 aA = *(const float4*)&As[kk*132 + i0];
            float4 aB = *(const float4*)&As[kk*132 + i0 + 4];
            u64 b01, b23, b45, b67;
            LDS_2x64(b01, b23, bAddr);
            LDS_2x64(b45, b67, bAddr + 16);
            (void)aAddr;
            float av[8] = {aA.x,aA.y,aA.z,aA.w,aB.x,aB.y,aB.z,aB.w};
            #pragma unroll
            for (int i = 0; i < 8; i++) {
                u64 ad; DUP2(ad, av[i]);
                FMA2(acc2[i][0], ad, b01, acc2[i][0]);
                FMA2(acc2[i][1], ad, b23, acc2[i][1]);
                FMA2(acc2[i][2], ad, b45, acc2[i][2]);
                FMA2(acc2[i][3], ad, b67, acc2[i][3]);
            }
        }
    }

    if (c0 < SO) {
        float4 bb0 = *(const float4*)&b2[c0];
        float4 bb1 = *(const float4*)&b2[c0 + 4];
        float bb[8] = {bb0.x,bb0.y,bb0.z,bb0.w,bb1.x,bb1.y,bb1.z,bb1.w};
        #pragma unroll
        for (int ii = 0; ii < 8; ii++) {
            float v[8];
            #pragma unroll
            for (int jp = 0; jp < 4; jp++) {
                unsigned lo, hi;
                UNPK2(lo, hi, acc2[ii][jp]);
                v[2*jp]   = __uint_as_float(lo) + bb[2*jp];
                v[2*jp+1] = __uint_as_float(hi) + bb[2*jp+1];
            }
            size_t p = (size_t)row*SEQ + (i0 + ii);
            float* dst = g_lie + p*SO + c0;
            *(float4*)dst     = make_float4(v[0],v[1],v[2],v[3]);
            *(float4*)(dst+4) = make_float4(v[4],v[5],v[6],v[7]);
        }
    }
}

// ---------------- warp 16x16 matmul (FFMA2, A preloaded) -------------------
__device__ __forceinline__ void wmm2(const float* __restrict__ A,
                                     unsigned Bsh,       // shared addr of B base
                                     float reg[2][4], int r0, int c0)
{
    float a0[16], a1[16];
    #pragma unroll
    for (int q = 0; q < 4; q++) {
        float4 v0 = *(const float4*)&A[(r0  )*20 + 4*q];
        float4 v1 = *(const float4*)&A[(r0+1)*20 + 4*q];
        a0[4*q]=v0.x; a0[4*q+1]=v0.y; a0[4*q+2]=v0.z; a0[4*q+3]=v0.w;
        a1[4*q]=v1.x; a1[4*q+1]=v1.y; a1[4*q+2]=v1.z; a1[4*q+3]=v1.w;
    }
    u64 c00=0ull, c01=0ull, c10=0ull, c11=0ull;
    #pragma unroll
    for (int k = 0; k < 16; k++) {
        u64 b0, b1;
        LDS_2x64(b0, b1, Bsh + (k*20 + c0)*4);
        u64 ad0, ad1;
        DUP2(ad0, a0[k]); DUP2(ad1, a1[k]);
        FMA2(c00, ad0, b0, c00); FMA2(c01, ad0, b1, c01);
        FMA2(c10, ad1, b0, c10); FMA2(c11, ad1, b1, c11);
    }
    unsigned lo, hi;
    UNPK2(lo, hi, c00); reg[0][0]=__uint_as_float(lo); reg[0][1]=__uint_as_float(hi);
    UNPK2(lo, hi, c01); reg[0][2]=__uint_as_float(lo); reg[0][3]=__uint_as_float(hi);
    UNPK2(lo, hi, c10); reg[1][0]=__uint_as_float(lo); reg[1][1]=__uint_as_float(hi);
    UNPK2(lo, hi, c11); reg[1][2]=__uint_as_float(lo); reg[1][3]=__uint_as_float(hi);
}

__device__ __forceinline__ void wstore20(float* __restrict__ C, const float reg[2][4],
                                         int r0, int c0)
{
    *(float4*)&C[(r0  )*20 + c0] = make_float4(reg[0][0],reg[0][1],reg[0][2],reg[0][3]);
    *(float4*)&C[(r0+1)*20 + c0] = make_float4(reg[1][0],reg[1][1],reg[1][2],reg[1][3]);
}

// ---------------- kernel D: expm + aggregate -------------------------------
__global__ void __launch_bounds__(128, 6)
expm_kernel(const float* __restrict__ xm_g, float* __restrict__ Tout)
{
    __shared__ __align__(16) float mm[4*4*320];
    int t = threadIdx.x, lane = t & 31, w = t >> 5;
    float* Abuf  = mm + w*1280;
    float* A2buf = Abuf + 320;
    float* A3buf = Abuf + 640;
    float* Tbuf  = Abuf + 960;
    unsigned AbufSh  = (unsigned)__cvta_generic_to_shared(Abuf);
    unsigned A3bufSh = AbufSh + 640*4;
    unsigned TbufSh  = AbufSh + 960*4;

    int r0m = (lane >> 2) * 2;
    int c0m = (lane & 3)  * 4;

    const float c3=1.f/6.f, c4=1.f/24.f, c5=1.f/120.f;
    const float c6=1.f/720.f, c7=1.f/5040.f, c8=1.f/40320.f, c9=1.f/362880.f;

    int p0 = blockIdx.x*64 + w*16;

    for (int m = 0; m < 16; m++) {
        int p   = p0 + m;
        int row = p >> 7;
        int i   = p & 127;
        int b   = row >> 7;

        // scatter lie -> skew A
        const float* lrow = g_lie + (size_t)p*SO;
        if (lane < 16) Abuf[lane*20 + lane] = 0.f;
        #pragma unroll
        for (int q = 0; q < 4; q++) {
            int l = lane + 32*q;
            if (l < SO) {
                float v = lrow[l];
                int rI = c_tri_r[l], cI = c_tri_c[l];
                Abuf[rI*20 + cI] =  v;
                Abuf[cI*20 + rI] = -v;
            }
        }
        __syncwarp();

        // inf-norm -> scaling exponent
        int myr = lane & 15;
        float4 n0 = *(const float4*)&Abuf[myr*20     ];
        float4 n1 = *(const float4*)&Abuf[myr*20 +  4];
        float4 n2 = *(const float4*)&Abuf[myr*20 +  8];
        float4 n3 = *(const float4*)&Abuf[myr*20 + 12];
        float rs = fabsf(n0.x)+fabsf(n0.y)+fabsf(n0.z)+fabsf(n0.w)
                 + fabsf(n1.x)+fabsf(n1.y)+fabsf(n1.z)+fabsf(n1.w)
                 + fabsf(n2.x)+fabsf(n2.y)+fabsf(n2.z)+fabsf(n2.w)
                 + fabsf(n3.x)+fabsf(n3.y)+fabsf(n3.z)+fabsf(n3.w);
        #pragma unroll
        for (int off = 8; off; off >>= 1)
            rs = fmaxf(rs, __shfl_xor_sync(0xffffffffu, rs, off));
        int sct = 0;
        if (rs > 1.f) { sct = (int)ceilf(log2f(rs)); if (sct > 12) sct = 12; }
        float scale = __uint_as_float((uint32_t)(127 - sct) << 23);
        #pragma unroll
        for (int q = 0; q < 8; q++) {
            int e = lane + 32*q;
            int rI = e >> 4, cI = e & 15;
            Abuf[rI*20 + cI] *= scale;
        }
        __syncwarp();

        float reg[2][4];
        // A2 = A*A
        wmm2(Abuf, AbufSh, reg, r0m, c0m);
        wstore20(A2buf, reg, r0m, c0m);  __syncwarp();
        // A3 = A2*A
        wmm2(A2buf, AbufSh, reg, r0m, c0m);
        wstore20(A3buf, reg, r0m, c0m);  __syncwarp();

        // B2 = c6 I + c7 A + c8 A2 + c9 A3  -> Tbuf (tiles read from smem)
        {
            float4 a0v  = *(const float4*)&Abuf [(r0m  )*20 + c0m];
            float4 a1v  = *(const float4*)&Abuf [(r0m+1)*20 + c0m];
            float4 p0v  = *(const float4*)&A2buf[(r0m  )*20 + c0m];
            float4 p1v  = *(const float4*)&A2buf[(r0m+1)*20 + c0m];
            float4 q0v  = *(const float4*)&A3buf[(r0m  )*20 + c0m];
            float4 q1v  = *(const float4*)&A3buf[(r0m+1)*20 + c0m];
            float tA [2][4] = {{a0v.x,a0v.y,a0v.z,a0v.w},{a1v.x,a1v.y,a1v.z,a1v.w}};
            float tA2[2][4] = {{p0v.x,p0v.y,p0v.z,p0v.w},{p1v.x,p1v.y,p1v.z,p1v.w}};
            float tA3[2][4] = {{q0v.x,q0v.y,q0v.z,q0v.w},{q1v.x,q1v.y,q1v.z,q1v.w}};
            #pragma unroll
            for (int ii = 0; ii < 2; ii++)
                #pragma unroll
                for (int jj = 0; jj < 4; jj++) {
                    float v = fmaf(c7, tA[ii][jj], fmaf(c8, tA2[ii][jj], c9 * tA3[ii][jj]));
                    if (r0m + ii == c0m + jj) v += c6;
                    reg[ii][jj] = v;
                }
            wstore20(Tbuf, reg, r0m, c0m);  __syncwarp();
        }

        // reg = A3*B2 + B1 -> Tbuf
        wmm2(A3buf, TbufSh, reg, r0m, c0m);  __syncwarp();
        {
            float4 a0v  = *(const float4*)&Abuf [(r0m  )*20 + c0m];
            float4 a1v  = *(const float4*)&Abuf [(r0m+1)*20 + c0m];
            float4 p0v  = *(const float4*)&A2buf[(r0m  )*20 + c0m];
            float4 p1v  = *(const float4*)&A2buf[(r0m+1)*20 + c0m];
            float tA [2][4] = {{a0v.x,a0v.y,a0v.z,a0v.w},{a1v.x,a1v.y,a1v.z,a1v.w}};
            float tA2[2][4] = {{p0v.x,p0v.y,p0v.z,p0v.w},{p1v.x,p1v.y,p1v.z,p1v.w}};
            #pragma unroll
            for (int ii = 0; ii < 2; ii++)
                #pragma unroll
                for (int jj = 0; jj < 4; jj++) {
                    reg[ii][jj] += fmaf(c4, tA[ii][jj], c5 * tA2[ii][jj]);
                    if (r0m + ii == c0m + jj) reg[ii][jj] += c3;
                }
            wstore20(Tbuf, reg, r0m, c0m);  __syncwarp();
        }

        // reg = A3*(B1 + A3*B2) + B0
        wmm2(A3buf, TbufSh, reg, r0m, c0m);
        {
            float4 a0v  = *(const float4*)&Abuf [(r0m  )*20 + c0m];
            float4 a1v  = *(const float4*)&Abuf [(r0m+1)*20 + c0m];
            float4 p0v  = *(const float4*)&A2buf[(r0m  )*20 + c0m];
            float4 p1v  = *(const float4*)&A2buf[(r0m+1)*20 + c0m];
            float tA [2][4] = {{a0v.x,a0v.y,a0v.z,a0v.w},{a1v.x,a1v.y,a1v.z,a1v.w}};
            float tA2[2][4] = {{p0v.x,p0v.y,p0v.z,p0v.w},{p1v.x,p1v.y,p1v.z,p1v.w}};
            #pragma unroll
            for (int ii = 0; ii < 2; ii++)
                #pragma unroll
                for (int jj = 0; jj < 4; jj++) {
                    reg[ii][jj] += fmaf(0.5f, tA2[ii][jj], tA[ii][jj]);
                    if (r0m + ii == c0m + jj) reg[ii][jj] += 1.f;
                }
        }

        // squarings
        for (int q = 0; q < sct; q++) {
            __syncwarp();
            wstore20(Tbuf, reg, r0m, c0m);
            __syncwarp();
            wmm2(Tbuf, TbufSh, reg, r0m, c0m);
        }

        // write T_all
        float* dst = Tout + (size_t)p*256;
        *(float4*)(dst + (r0m  )*16 + c0m) = make_float4(reg[0][0],reg[0][1],reg[0][2],reg[0][3]);
        *(float4*)(dst + (r0m+1)*16 + c0m) = make_float4(reg[1][0],reg[1][1],reg[1][2],reg[1][3]);

        // transported & settled
        float4 xv = *(const float4*)&xm_g[((size_t)b*SEQ + i)*DM + c0m];
        float p0v = reg[0][0]*xv.x + reg[0][1]*xv.y + reg[0][2]*xv.z + reg[0][3]*xv.w;
        float p1v = reg[1][0]*xv.x + reg[1][1]*xv.y + reg[1][2]*xv.z + reg[1][3]*xv.w;
        p0v += __shfl_xor_sync(0xffffffffu, p0v, 1);
        p0v += __shfl_xor_sync(0xffffffffu, p0v, 2);
        p1v += __shfl_xor_sync(0xffffffffu, p1v, 1);
        p1v += __shfl_xor_sync(0xffffffffu, p1v, 2);
        if ((lane & 3) == 0) {
            float wgt = g_attn[row*SEQ + i];
            atomicAdd(&g_settled[row*DM + r0m    ], wgt * p0v);
            atomicAdd(&g_settled[row*DM + r0m + 1], wgt * p1v);
        }
        __syncwarp();
    }
}

// ---------------- kernel E: out projection ---------------------------------
__global__ void __launch_bounds__(256)
out_kernel(const float* __restrict__ Wo, const float* __restrict__ bo,
           float* __restrict__ out)
{
    int gid = blockIdx.x*256 + threadIdx.x;    // 8192
    int row = gid >> 4, d = gid & 15;
    float acc = bo[d];
    #pragma unroll
    for (int e = 0; e < DM; e++)
        acc = fmaf(Wo[d*DM + e], g_settled[row*DM + e], acc);
    out[gid] = acc;
}

// ---------------- launch ----------------------------------------------------
extern "C" void kernel_launch(void* const* d_in, const int* in_sizes, int n_in,
                              void* d_out, int out_size)
{
    const float* xl  = (const float*)d_in[0];
    const float* xmm = (const float*)d_in[1];
    const float* Wq  = (const float*)d_in[2];
    const float* bq  = (const float*)d_in[3];
    const float* Wk  = (const float*)d_in[4];
    const float* bk  = (const float*)d_in[5];
    const float* W1  = (const float*)d_in[6];
    const float* b1  = (const float*)d_in[7];
    const float* W2  = (const float*)d_in[8];
    const float* b2  = (const float*)d_in[9];
    const float* Wo  = (const float*)d_in[10];
    const float* bo  = (const float*)d_in[11];

    float* out  = (float*)d_out;
    float* Tout = out + NB*SEQ*DM;      // T_all follows out

    static bool attr_set = false;
    if (!attr_set) {
        cudaFuncSetAttribute(attn_kernel, cudaFuncAttributeMaxDynamicSharedMemorySize, AT_BYTES);
        attr_set = true;
    }

    prep_kernel<<<dim3(8,8), 256>>>(xl, Wq, bq, Wk, bk, W1);
    attn_kernel<<<16, 256, AT_BYTES>>>();
    pair_kernel<<<ROWS, 256>>>(b1, W2, b2);
    expm_kernel<<<1024, 128>>>(xmm, Tout);
    out_kernel<<<32, 256>>>(Wo, bo, out);
}

// round 6
// speedup vs baseline: 1.0483x; 1.0483x over previous
#include <cuda_runtime.h>
#include <math.h>
#include <stdint.h>

#define NB 4
#define SEQ 128
#define DL 128
#define DM 16
#define SO 120
#define ROWS (NB*SEQ)        // 512

typedef unsigned long long u64;

// packed fp32x2 FMA (sm_100+): d = a*b + c on both 32-bit halves
#define FMA2(d,a,b,c) asm("fma.rn.f32x2 %0, %1, %2, %3;" : "=l"(d) : "l"(a), "l"(b), "l"(c))
#define DUP2(d,s)     asm("mov.b64 %0, {%1, %1};" : "=l"(d) : "r"(__float_as_uint(s)))
#define UNPK2(lo,hi,p) asm("mov.b64 {%0, %1}, %2;" : "=r"(lo), "=r"(hi) : "l"(p))
#define LDS_2x64(p0,p1,addr) asm volatile("ld.shared.v2.b64 {%0, %1}, [%2];" : "=l"(p0), "=l"(p1) : "r"(addr))

// ---------------- scratch (device globals; no allocations allowed) ----------
__device__ float g_Q[ROWS*DL];
__device__ float g_K[ROWS*DL];
__device__ float g_U[ROWS*256];
__device__ float g_attn[NB*SEQ*SEQ];
__device__ float g_lie[(size_t)NB*SEQ*SEQ*SO];   // 31.5 MB
__device__ float g_settled[ROWS*DM];

__constant__ int c_tri_r[120] = {
 0,0,0,0,0,0,0,0,0,0,0,0,0,0,0,
 1,1,1,1,1,1,1,1,1,1,1,1,1,1,
 2,2,2,2,2,2,2,2,2,2,2,2,2,
 3,3,3,3,3,3,3,3,3,3,3,3,
 4,4,4,4,4,4,4,4,4,4,4,
 5,5,5,5,5,5,5,5,5,5,
 6,6,6,6,6,6,6,6,6,
 7,7,7,7,7,7,7,7,
 8,8,8,8,8,8,8,
 9,9,9,9,9,9,
 10,10,10,10,10,
 11,11,11,11,
 12,12,12,
 13,13,
 14};
__constant__ int c_tri_c[120] = {
 1,2,3,4,5,6,7,8,9,10,11,12,13,14,15,
 2,3,4,5,6,7,8,9,10,11,12,13,14,15,
 3,4,5,6,7,8,9,10,11,12,13,14,15,
 4,5,6,7,8,9,10,11,12,13,14,15,
 5,6,7,8,9,10,11,12,13,14,15,
 6,7,8,9,10,11,12,13,14,15,
 7,8,9,10,11,12,13,14,15,
 8,9,10,11,12,13,14,15,
 9,10,11,12,13,14,15,
 10,11,12,13,14,15,
 11,12,13,14,15,
 12,13,14,15,
 13,14,15,
 14,15,
 15};

__device__ __forceinline__ float ftanh(float x) {
    float y;
    asm("tanh.approx.f32 %0, %1;" : "=f"(y) : "f"(x));
    return y;
}

// ---------------- kernel A: tiled GEMM  C[512 x 512] = X @ [Wq;Wk;W1]^T ----
__global__ void __launch_bounds__(256)
prep_kernel(const float* __restrict__ xl,
            const float* __restrict__ Wq, const float* __restrict__ bq,
            const float* __restrict__ Wk, const float* __restrict__ bk,
            const float* __restrict__ W1)
{
    __shared__ __align__(16) float Xs[64*64];
    __shared__ __align__(16) float Wt[64*68];

    int bx = blockIdx.x, by = blockIdx.y;
    int t  = threadIdx.x;
    int tx = t & 15, ty = t >> 4;

    const float* src;
    if      (by < 2) src = Wq + (by    )*64*DL;
    else if (by < 4) src = Wk + (by - 2)*64*DL;
    else             src = W1 + (by - 4)*64*DL;

    float acc[4][4];
    #pragma unroll
    for (int i = 0; i < 4; i++)
        #pragma unroll
        for (int j = 0; j < 4; j++) acc[i][j] = 0.f;

    for (int k0 = 0; k0 < DL; k0 += 64) {
        __syncthreads();
        #pragma unroll
        for (int s = 0; s < 16; s++) {
            int idx = t + 256*s;
            int r = idx >> 6, k = idx & 63;
            Xs[r*64 + k] = xl[(bx*64 + r)*DL + k0 + k];
            Wt[k*68 + r] = src[r*DL + k0 + k];
        }
        __syncthreads();

        #pragma unroll 8
        for (int k = 0; k < 64; k++) {
            float4 bv = *(const float4*)&Wt[k*68 + tx*4];
            #pragma unroll
            for (int i = 0; i < 4; i++) {
                float a = Xs[(ty*4 + i)*64 + k];
                acc[i][0] = fmaf(a, bv.x, acc[i][0]);
                acc[i][1] = fmaf(a, bv.y, acc[i][1]);
                acc[i][2] = fmaf(a, bv.z, acc[i][2]);
                acc[i][3] = fmaf(a, bv.w, acc[i][3]);
            }
        }
    }

    #pragma unroll
    for (int i = 0; i < 4; i++) {
        int rowg = bx*64 + ty*4 + i;
        int c0   = tx*4;
        if (by < 2) {
            int col = by*64 + c0;
            *(float4*)&g_Q[rowg*DL + col] =
                make_float4(acc[i][0]+bq[col], acc[i][1]+bq[col+1],
                            acc[i][2]+bq[col+2], acc[i][3]+bq[col+3]);
        } else if (by < 4) {
            int col = (by-2)*64 + c0;
            *(float4*)&g_K[rowg*DL + col] =
                make_float4(acc[i][0]+bk[col], acc[i][1]+bk[col+1],
                            acc[i][2]+bk[col+2], acc[i][3]+bk[col+3]);
        } else {
            int col = (by-4)*64 + c0;
            *(float4*)&g_U[rowg*256 + col] =
                make_float4(acc[i][0], acc[i][1], acc[i][2], acc[i][3]);
        }
    }
}

// ---------------- kernel B: attention softmax (+ zero g_settled) -----------
#define AT_QS 0
#define AT_KT (AT_QS + 32*128)
#define AT_S  (AT_KT + 128*132)
#define AT_FLOATS (AT_S + 32*132)
#define AT_BYTES  (AT_FLOATS*4)

__global__ void __launch_bounds__(256)
attn_kernel()
{
    extern __shared__ float sm[];
    float* Qs = sm + AT_QS;
    float* Kt = sm + AT_KT;
    float* S  = sm + AT_S;

    int b  = blockIdx.x >> 2;
    int jt = (blockIdx.x & 3) * 32;
    int t  = threadIdx.x;
    int tx = t & 15, ty = t >> 4;

    for (int z = t; z < 512; z += 256) g_settled[blockIdx.x*512 + z] = 0.f;

    for (int idx = t; idx < 32*128; idx += 256) {
        int j = idx >> 7, k = idx & 127;
        Qs[j*128 + k] = g_Q[(b*SEQ + jt + j)*DL + k];
    }
    for (int idx = t; idx < 128*128; idx += 256) {
        int i = idx >> 7, k = idx & 127;
        Kt[k*132 + i] = g_K[(b*SEQ + i)*DL + k];
    }
    __syncthreads();

    float acc[2][8];
    #pragma unroll
    for (int i = 0; i < 2; i++)
        #pragma unroll
        for (int j = 0; j < 8; j++) acc[i][j] = 0.f;

    int j0 = ty*2, i0 = tx*8;
    #pragma unroll 4
    for (int k = 0; k < 128; k++) {
        float q0 = Qs[(j0  )*128 + k];
        float q1 = Qs[(j0+1)*128 + k];
        float4 k0v = *(const float4*)&Kt[k*132 + i0];
        float4 k1v = *(const float4*)&Kt[k*132 + i0 + 4];
        acc[0][0]=fmaf(q0,k0v.x,acc[0][0]); acc[0][1]=fmaf(q0,k0v.y,acc[0][1]);
        acc[0][2]=fmaf(q0,k0v.z,acc[0][2]); acc[0][3]=fmaf(q0,k0v.w,acc[0][3]);
        acc[0][4]=fmaf(q0,k1v.x,acc[0][4]); acc[0][5]=fmaf(q0,k1v.y,acc[0][5]);
        acc[0][6]=fmaf(q0,k1v.z,acc[0][6]); acc[0][7]=fmaf(q0,k1v.w,acc[0][7]);
        acc[1][0]=fmaf(q1,k0v.x,acc[1][0]); acc[1][1]=fmaf(q1,k0v.y,acc[1][1]);
        acc[1][2]=fmaf(q1,k0v.z,acc[1][2]); acc[1][3]=fmaf(q1,k0v.w,acc[1][3]);
        acc[1][4]=fmaf(q1,k1v.x,acc[1][4]); acc[1][5]=fmaf(q1,k1v.y,acc[1][5]);
        acc[1][6]=fmaf(q1,k1v.z,acc[1][6]); acc[1][7]=fmaf(q1,k1v.w,acc[1][7]);
    }
    const float sc = 0.08838834764831845f;
    #pragma unroll
    for (int i = 0; i < 2; i++) {
        *(float4*)&S[(j0+i)*132 + i0] =
            make_float4(acc[i][0]*sc, acc[i][1]*sc, acc[i][2]*sc, acc[i][3]*sc);
        *(float4*)&S[(j0+i)*132 + i0 + 4] =
            make_float4(acc[i][4]*sc, acc[i][5]*sc, acc[i][6]*sc, acc[i][7]*sc);
    }
    __syncthreads();

    int w = t >> 5, lane = t & 31;
    for (int q = 0; q < 4; q++) {
        int r = w*4 + q;
        float v0 = S[r*132 + lane      ];
        float v1 = S[r*132 + lane + 32 ];
        float v2 = S[r*132 + lane + 64 ];
        float v3 = S[r*132 + lane + 96 ];
        float mx = fmaxf(fmaxf(v0,v1), fmaxf(v2,v3));
        #pragma unroll
        for (int off = 16; off; off >>= 1)
            mx = fmaxf(mx, __shfl_xor_sync(0xffffffffu, mx, off));
        float e0 = expf(v0-mx), e1 = expf(v1-mx), e2 = expf(v2-mx), e3 = expf(v3-mx);
        float sum = e0+e1+e2+e3;
        #pragma unroll
        for (int off = 16; off; off >>= 1)
            sum += __shfl_xor_sync(0xffffffffu, sum, off);
        float inv = 1.f/sum;
        float* dst = g_attn + (b*SEQ + jt + r)*SEQ;
        dst[lane     ] = e0*inv;
        dst[lane + 32] = e1*inv;
        dst[lane + 64] = e2*inv;
        dst[lane + 96] = e3*inv;
    }
}

// ---------------- kernel C: pairwise MLP GEMM -> g_lie  (FFMA2) ------------
__global__ void __launch_bounds__(256, 2)
pair_kernel(const float* __restrict__ b1, const float* __restrict__ W2,
            const float* __restrict__ b2)
{
    __shared__ __align__(16) float Ujb[256];
    __shared__ __align__(16) float As[32*132];   // [kk][i]
    __shared__ __align__(16) float Bs[32*132];   // [kk][c]

    int row = blockIdx.x;          // b*128 + j
    int b   = row >> 7;
    int t   = threadIdx.x;

    Ujb[t] = g_U[row*256 + t] + b1[t];

    int i0 = (t & 15) * 8;
    int c0 = (t >> 4) * 8;

    unsigned bsBase = (unsigned)__cvta_generic_to_shared(Bs) + c0*4;

    u64 acc2[8][4];
    #pragma unroll
    for (int i = 0; i < 8; i++)
        #pragma unroll
        for (int j = 0; j < 4; j++) acc2[i][j] = 0ull;

    for (int k0 = 0; k0 < 256; k0 += 32) {
        __syncthreads();
        #pragma unroll
        for (int s = 0; s < 16; s++) {
            int idx = t + 256*s;          // 4096
            int i = idx >> 5, kk = idx & 31;
            float u = g_U[(b*SEQ + i)*256 + k0 + kk];
            As[kk*132 + i] = ftanh(Ujb[k0 + kk] - u);
        }
        #pragma unroll
        for (int s = 0; s < 15; s++) {
            int idx = t + 256*s;          // 3840
            int c = idx >> 5, kk = idx & 31;
            Bs[kk*132 + c] = W2[c*256 + k0 + kk];
        }
        { int c = 120 + (t >> 5), kk = t & 31; Bs[kk*132 + c] = 0.f; }
        __syncthreads();

        #pragma unroll
        for (int kk = 0; kk < 32; kk++) {
            unsigned bAddr = bsBase + kk*132*4;
            float4 aA = *(const float4*)&As[kk*132 + i0];
            float4 aB = *(const float4*)&As[kk*132 + i0 + 4];
            u64 b01, b23, b45, b67;
            LDS_2x64(b01, b23, bAddr);
            LDS_2x64(b45, b67, bAddr + 16);
            float av[8] = {aA.x,aA.y,aA.z,aA.w,aB.x,aB.y,aB.z,aB.w};
            #pragma unroll
            for (int i = 0; i < 8; i++) {
                u64 ad; DUP2(ad, av[i]);
                FMA2(acc2[i][0], ad, b01, acc2[i][0]);
                FMA2(acc2[i][1], ad, b23, acc2[i][1]);
                FMA2(acc2[i][2], ad, b45, acc2[i][2]);
                FMA2(acc2[i][3], ad, b67, acc2[i][3]);
            }
        }
    }

    if (c0 < SO) {
        float4 bb0 = *(const float4*)&b2[c0];
        float4 bb1 = *(const float4*)&b2[c0 + 4];
        float bb[8] = {bb0.x,bb0.y,bb0.z,bb0.w,bb1.x,bb1.y,bb1.z,bb1.w};
        #pragma unroll
        for (int ii = 0; ii < 8; ii++) {
            float v[8];
            #pragma unroll
            for (int jp = 0; jp < 4; jp++) {
                unsigned lo, hi;
                UNPK2(lo, hi, acc2[ii][jp]);
                v[2*jp]   = __uint_as_float(lo) + bb[2*jp];
                v[2*jp+1] = __uint_as_float(hi) + bb[2*jp+1];
            }
            size_t p = (size_t)row*SEQ + (i0 + ii);
            float* dst = g_lie + p*SO + c0;
            *(float4*)dst     = make_float4(v[0],v[1],v[2],v[3]);
            *(float4*)(dst+4) = make_float4(v[4],v[5],v[6],v[7]);
        }
    }
}

// ---------------- paired warp 16x16 matmul (scalar FMA, 2 matrices) --------
// Lane owns row r0 = lane>>1, cols c0..c0+7 with c0 = (lane&1)*8.
__device__ __forceinline__ void wmm_pair(
    const float* __restrict__ A0, const float* __restrict__ B0,
    const float* __restrict__ A1, const float* __restrict__ B1,
    float R0[8], float R1[8], int r0, int c0)
{
    float a0[16], a1[16];
    #pragma unroll
    for (int q = 0; q < 4; q++) {
        float4 v0 = *(const float4*)&A0[r0*20 + 4*q];
        float4 v1 = *(const float4*)&A1[r0*20 + 4*q];
        a0[4*q]=v0.x; a0[4*q+1]=v0.y; a0[4*q+2]=v0.z; a0[4*q+3]=v0.w;
        a1[4*q]=v1.x; a1[4*q+1]=v1.y; a1[4*q+2]=v1.z; a1[4*q+3]=v1.w;
    }
    #pragma unroll
    for (int j = 0; j < 8; j++) { R0[j] = 0.f; R1[j] = 0.f; }
    #pragma unroll
    for (int k = 0; k < 16; k++) {
        float4 p0 = *(const float4*)&B0[k*20 + c0];
        float4 p1 = *(const float4*)&B0[k*20 + c0 + 4];
        float4 q0 = *(const float4*)&B1[k*20 + c0];
        float4 q1 = *(const float4*)&B1[k*20 + c0 + 4];
        R0[0]=fmaf(a0[k],p0.x,R0[0]); R0[1]=fmaf(a0[k],p0.y,R0[1]);
        R0[2]=fmaf(a0[k],p0.z,R0[2]); R0[3]=fmaf(a0[k],p0.w,R0[3]);
        R0[4]=fmaf(a0[k],p1.x,R0[4]); R0[5]=fmaf(a0[k],p1.y,R0[5]);
        R0[6]=fmaf(a0[k],p1.z,R0[6]); R0[7]=fmaf(a0[k],p1.w,R0[7]);
        R1[0]=fmaf(a1[k],q0.x,R1[0]); R1[1]=fmaf(a1[k],q0.y,R1[1]);
        R1[2]=fmaf(a1[k],q0.z,R1[2]); R1[3]=fmaf(a1[k],q0.w,R1[3]);
        R1[4]=fmaf(a1[k],q1.x,R1[4]); R1[5]=fmaf(a1[k],q1.y,R1[5]);
        R1[6]=fmaf(a1[k],q1.z,R1[6]); R1[7]=fmaf(a1[k],q1.w,R1[7]);
    }
}

__device__ __forceinline__ void st8(float* __restrict__ C, const float R[8],
                                    int r0, int c0)
{
    *(float4*)&C[r0*20 + c0    ] = make_float4(R[0],R[1],R[2],R[3]);
    *(float4*)&C[r0*20 + c0 + 4] = make_float4(R[4],R[5],R[6],R[7]);
}

// ---------------- kernel D: expm + aggregate (2 matrices / warp) -----------
#define EXPM_BLOCKS 740    // 5 blocks/SM * 148 SMs

__global__ void __launch_bounds__(128, 5)
expm_kernel(const float* __restrict__ xm_g, float* __restrict__ Tout)
{
    __shared__ __align__(16) float mm[4*2*4*320];   // 40 KB
    int t = threadIdx.x, lane = t & 31, w = t >> 5;
    float* M0  = mm + w*(2*4*320);
    float* A0b = M0;        float* A20 = M0 + 320;
    float* A30 = M0 + 640;  float* T0  = M0 + 960;
    float* M1  = M0 + 1280;
    float* A1b = M1;        float* A21 = M1 + 320;
    float* A31 = M1 + 640;  float* T1  = M1 + 960;

    int r0 = lane >> 1;          // row 0..15
    int c0 = (lane & 1) * 8;     // col 0 or 8

    const float c3=1.f/6.f, c4=1.f/24.f, c5=1.f/120.f;
    const float c6=1.f/720.f, c7=1.f/5040.f, c8=1.f/40320.f, c9=1.f/362880.f;

    int gw = blockIdx.x*4 + w;            // global warp id
    int gstride = EXPM_BLOCKS*4;

    for (int pp = gw; pp < 32768; pp += gstride) {
        int p0 = pp*2, p1 = p0 + 1;
        int row = p0 >> 7;                // b*128 + j  (same for both)
        int i0  = p0 & 127, i1 = i0 + 1;
        int b   = row >> 7;

        // ---- scatter lie -> skew (both matrices) ----
        const float* lr0 = g_lie + (size_t)p0*SO;
        const float* lr1 = g_lie + (size_t)p1*SO;
        if (lane < 16) { A0b[lane*20 + lane] = 0.f; A1b[lane*20 + lane] = 0.f; }
        #pragma unroll
        for (int q = 0; q < 4; q++) {
            int l = lane + 32*q;
            if (l < SO) {
                int rI = c_tri_r[l], cI = c_tri_c[l];
                float v0 = lr0[l], v1 = lr1[l];
                A0b[rI*20 + cI] =  v0;  A0b[cI*20 + rI] = -v0;
                A1b[rI*20 + cI] =  v1;  A1b[cI*20 + rI] = -v1;
            }
        }
        __syncwarp();

        // ---- joint inf-norm -> shared scaling exponent ----
        float4 x0 = *(const float4*)&A0b[r0*20 + c0];
        float4 x1 = *(const float4*)&A0b[r0*20 + c0 + 4];
        float4 y0 = *(const float4*)&A1b[r0*20 + c0];
        float4 y1 = *(const float4*)&A1b[r0*20 + c0 + 4];
        float s0 = fabsf(x0.x)+fabsf(x0.y)+fabsf(x0.z)+fabsf(x0.w)
                 + fabsf(x1.x)+fabsf(x1.y)+fabsf(x1.z)+fabsf(x1.w);
        float s1 = fabsf(y0.x)+fabsf(y0.y)+fabsf(y0.z)+fabsf(y0.w)
                 + fabsf(y1.x)+fabsf(y1.y)+fabsf(y1.z)+fabsf(y1.w);
        s0 += __shfl_xor_sync(0xffffffffu, s0, 1);
        s1 += __shfl_xor_sync(0xffffffffu, s1, 1);
        float rsm = fmaxf(s0, s1);
        #pragma unroll
        for (int off = 2; off < 32; off <<= 1)
            rsm = fmaxf(rsm, __shfl_xor_sync(0xffffffffu, rsm, off));
        int sct = 0;
        if (rsm > 1.f) { sct = (int)ceilf(log2f(rsm)); if (sct > 12) sct = 12; }
        float scale = __uint_as_float((uint32_t)(127 - sct) << 23);

        // scale in registers, write back
        x0.x*=scale; x0.y*=scale; x0.z*=scale; x0.w*=scale;
        x1.x*=scale; x1.y*=scale; x1.z*=scale; x1.w*=scale;
        y0.x*=scale; y0.y*=scale; y0.z*=scale; y0.w*=scale;
        y1.x*=scale; y1.y*=scale; y1.z*=scale; y1.w*=scale;
        *(float4*)&A0b[r0*20 + c0    ] = x0;
        *(float4*)&A0b[r0*20 + c0 + 4] = x1;
        *(float4*)&A1b[r0*20 + c0    ] = y0;
        *(float4*)&A1b[r0*20 + c0 + 4] = y1;
        __syncwarp();

        float R0[8], R1[8];
        // A2 = A*A
        wmm_pair(A0b, A0b, A1b, A1b, R0, R1, r0, c0);
        st8(A20, R0, r0, c0); st8(A21, R1, r0, c0);
        __syncwarp();
        // A3 = A2*A
        wmm_pair(A20, A0b, A21, A1b, R0, R1, r0, c0);
        st8(A30, R0, r0, c0); st8(A31, R1, r0, c0);
        __syncwarp();

        // ---- B2 = c6 I + c7 A + c8 A2 + c9 A3 -> T ----
        {
            float4 a30 = *(const float4*)&A30[r0*20 + c0];
            float4 a31 = *(const float4*)&A30[r0*20 + c0 + 4];
            float4 b30 = *(const float4*)&A31[r0*20 + c0];
            float4 b31 = *(const float4*)&A31[r0*20 + c0 + 4];
            float4 a20 = *(const float4*)&A20[r0*20 + c0];
            float4 a21 = *(const float4*)&A20[r0*20 + c0 + 4];
            float4 b20 = *(const float4*)&A21[r0*20 + c0];
            float4 b21 = *(const float4*)&A21[r0*20 + c0 + 4];
            float tA0[8] = {x0.x,x0.y,x0.z,x0.w,x1.x,x1.y,x1.z,x1.w};
            float tA1[8] = {y0.x,y0.y,y0.z,y0.w,y1.x,y1.y,y1.z,y1.w};
            float t20[8] = {a20.x,a20.y,a20.z,a20.w,a21.x,a21.y,a21.z,a21.w};
            float t21[8] = {b20.x,b20.y,b20.z,b20.w,b21.x,b21.y,b21.z,b21.w};
            float t30[8] = {a30.x,a30.y,a30.z,a30.w,a31.x,a31.y,a31.z,a31.w};
            float t31[8] = {b30.x,b30.y,b30.z,b30.w,b31.x,b31.y,b31.z,b31.w};
            #pragma unroll
            for (int j = 0; j < 8; j++) {
                float v0 = fmaf(c7, tA0[j], fmaf(c8, t20[j], c9 * t30[j]));
                float v1 = fmaf(c7, tA1[j], fmaf(c8, t21[j], c9 * t31[j]));
                if (r0 == c0 + j) { v0 += c6; v1 += c6; }
                R0[j] = v0; R1[j] = v1;
            }
            st8(T0, R0, r0, c0); st8(T1, R1, r0, c0);
        }
        __syncwarp();

        // ---- T = A3*B2 + (c3 I + c4 A + c5 A2) ----
        wmm_pair(A30, T0, A31, T1, R0, R1, r0, c0);
        __syncwarp();           // all lanes done reading T before overwrite
        {
            float4 a20 = *(const float4*)&A20[r0*20 + c0];
            float4 a21 = *(const float4*)&A20[r0*20 + c0 + 4];
            float4 b20 = *(const float4*)&A21[r0*20 + c0];
            float4 b21 = *(const float4*)&A21[r0*20 + c0 + 4];
            float4 a00 = *(const float4*)&A0b[r0*20 + c0];
            float4 a01 = *(const float4*)&A0b[r0*20 + c0 + 4];
            float4 b00 = *(const float4*)&A1b[r0*20 + c0];
            float4 b01 = *(const float4*)&A1b[r0*20 + c0 + 4];
            float tA0[8] = {a00.x,a00.y,a00.z,a00.w,a01.x,a01.y,a01.z,a01.w};
            float tA1[8] = {b00.x,b00.y,b00.z,b00.w,b01.x,b01.y,b01.z,b01.w};
            float t20[8] = {a20.x,a20.y,a20.z,a20.w,a21.x,a21.y,a21.z,a21.w};
            float t21[8] = {b20.x,b20.y,b20.z,b20.w,b21.x,b21.y,b21.z,b21.w};
            #pragma unroll
            for (int j = 0; j < 8; j++) {
                R0[j] += fmaf(c4, tA0[j], c5 * t20[j]);
                R1[j] += fmaf(c4, tA1[j], c5 * t21[j]);
                if (r0 == c0 + j) { R0[j] += c3; R1[j] += c3; }
            }
            st8(T0, R0, r0, c0); st8(T1, R1, r0, c0);
        }
        __syncwarp();

        // ---- R = A3*T + (I + A + A2/2) ----
        wmm_pair(A30, T0, A31, T1, R0, R1, r0, c0);
        {
            float4 a20 = *(const float4*)&A20[r0*20 + c0];
            float4 a21 = *(const float4*)&A20[r0*20 + c0 + 4];
            float4 b20 = *(const float4*)&A21[r0*20 + c0];
            float4 b21 = *(const float4*)&A21[r0*20 + c0 + 4];
            float4 a00 = *(const float4*)&A0b[r0*20 + c0];
            float4 a01 = *(const float4*)&A0b[r0*20 + c0 + 4];
            float4 b00 = *(const float4*)&A1b[r0*20 + c0];
            float4 b01 = *(const float4*)&A1b[r0*20 + c0 + 4];
            float tA0[8] = {a00.x,a00.y,a00.z,a00.w,a01.x,a01.y,a01.z,a01.w};
            float tA1[8] = {b00.x,b00.y,b00.z,b00.w,b01.x,b01.y,b01.z,b01.w};
            float t20[8] = {a20.x,a20.y,a20.z,a20.w,a21.x,a21.y,a21.z,a21.w};
            float t21[8] = {b20.x,b20.y,b20.z,b20.w,b21.x,b21.y,b21.z,b21.w};
            #pragma unroll
            for (int j = 0; j < 8; j++) {
                R0[j] += fmaf(0.5f, t20[j], tA0[j]);
                R1[j] += fmaf(0.5f, t21[j], tA1[j]);
                if (r0 == c0 + j) { R0[j] += 1.f; R1[j] += 1.f; }
            }
        }

        // ---- squarings (shared sct for the pair) ----
        for (int q = 0; q < sct; q++) {
            __syncwarp();
            st8(T0, R0, r0, c0); st8(T1, R1, r0, c0);
            __syncwarp();
            wmm_pair(T0, T0, T1, T1, R0, R1, r0, c0);
        }

        // ---- write T_all ----
        float* d0 = Tout + (size_t)p0*256 + r0*16 + c0;
        float* d1 = Tout + (size_t)p1*256 + r0*16 + c0;
        *(float4*)d0     = make_float4(R0[0],R0[1],R0[2],R0[3]);
        *(float4*)(d0+4) = make_float4(R0[4],R0[5],R0[6],R0[7]);
        *(float4*)d1     = make_float4(R1[0],R1[1],R1[2],R1[3]);
        *(float4*)(d1+4) = make_float4(R1[4],R1[5],R1[6],R1[7]);

        // ---- transported & settled ----
        float4 xv0a = *(const float4*)&xm_g[((size_t)b*SEQ + i0)*DM + c0];
        float4 xv0b = *(const float4*)&xm_g[((size_t)b*SEQ + i0)*DM + c0 + 4];
        float4 xv1a = *(const float4*)&xm_g[((size_t)b*SEQ + i1)*DM + c0];
        float4 xv1b = *(const float4*)&xm_g[((size_t)b*SEQ + i1)*DM + c0 + 4];
        float pd0 = R0[0]*xv0a.x + R0[1]*xv0a.y + R0[2]*xv0a.z + R0[3]*xv0a.w
                  + R0[4]*xv0b.x + R0[5]*xv0b.y + R0[6]*xv0b.z + R0[7]*xv0b.w;
        float pd1 = R1[0]*xv1a.x + R1[1]*xv1a.y + R1[2]*xv1a.z + R1[3]*xv1a.w
                  + R1[4]*xv1b.x + R1[5]*xv1b.y + R1[6]*xv1b.z + R1[7]*xv1b.w;
        pd0 += __shfl_xor_sync(0xffffffffu, pd0, 1);
        pd1 += __shfl_xor_sync(0xffffffffu, pd1, 1);
        if ((lane & 1) == 0) {
            float w0 = g_attn[row*SEQ + i0];
            float w1 = g_attn[row*SEQ + i1];
            atomicAdd(&g_settled[row*DM + r0], fmaf(w0, pd0, w1 * pd1));
        }
        __syncwarp();
    }
}

// ---------------- kernel E: out projection ---------------------------------
__global__ void __launch_bounds__(256)
out_kernel(const float* __restrict__ Wo, const float* __restrict__ bo,
           float* __restrict__ out)
{
    int gid = blockIdx.x*256 + threadIdx.x;    // 8192
    int row = gid >> 4, d = gid & 15;
    float acc = bo[d];
    #pragma unroll
    for (int e = 0; e < DM; e++)
        acc = fmaf(Wo[d*DM + e], g_settled[row*DM + e], acc);
    out[gid] = acc;
}

// ---------------- launch ----------------------------------------------------
extern "C" void kernel_launch(void* const* d_in, const int* in_sizes, int n_in,
                              void* d_out, int out_size)
{
    const float* xl  = (const float*)d_in[0];
    const float* xmm = (const float*)d_in[1];
    const float* Wq  = (const float*)d_in[2];
    const float* bq  = (const float*)d_in[3];
    const float* Wk  = (const float*)d_in[4];
    const float* bk  = (const float*)d_in[5];
    const float* W1  = (const float*)d_in[6];
    const float* b1  = (const float*)d_in[7];
    const float* W2  = (const float*)d_in[8];
    const float* b2  = (const float*)d_in[9];
    const float* Wo  = (const float*)d_in[10];
    const float* bo  = (const float*)d_in[11];

    float* out  = (float*)d_out;
    float* Tout = out + NB*SEQ*DM;      // T_all follows out

    static bool attr_set = false;
    if (!attr_set) {
        cudaFuncSetAttribute(attn_kernel, cudaFuncAttributeMaxDynamicSharedMemorySize, AT_BYTES);
        attr_set = true;
    }

    prep_kernel<<<dim3(8,8), 256>>>(xl, Wq, bq, Wk, bk, W1);
    attn_kernel<<<16, 256, AT_BYTES>>>();
    pair_kernel<<<ROWS, 256>>>(b1, W2, b2);
    expm_kernel<<<EXPM_BLOCKS, 128>>>(xmm, Tout);
    out_kernel<<<32, 256>>>(Wo, bo, out);
}

// round 7
// speedup vs baseline: 1.0839x; 1.0340x over previous
#include <cuda_runtime.h>
#include <math.h>
#include <stdint.h>

#define NB 4
#define SEQ 128
#define DL 128
#define DM 16
#define SO 120
#define ROWS (NB*SEQ)        // 512

typedef unsigned long long u64;

// packed fp32x2 FMA (sm_100+): d = a*b + c on both 32-bit halves
#define FMA2(d,a,b,c) asm("fma.rn.f32x2 %0, %1, %2, %3;" : "=l"(d) : "l"(a), "l"(b), "l"(c))
#define DUP2(d,s)     asm("mov.b64 %0, {%1, %1};" : "=l"(d) : "r"(__float_as_uint(s)))
#define UNPK2(lo,hi,p) asm("mov.b64 {%0, %1}, %2;" : "=r"(lo), "=r"(hi) : "l"(p))
#define LDS_2x64(p0,p1,addr) asm volatile("ld.shared.v2.b64 {%0, %1}, [%2];" : "=l"(p0), "=l"(p1) : "r"(addr))

// ---------------- scratch (device globals; no allocations allowed) ----------
__device__ float g_Q[ROWS*DL];
__device__ float g_K[ROWS*DL];
__device__ float g_U[ROWS*256];
__device__ float g_attn[NB*SEQ*SEQ];
__device__ float g_lie[(size_t)NB*SEQ*SEQ*SO];   // 31.5 MB
__device__ float g_settled[ROWS*DM];

__constant__ int c_tri_r[120] = {
 0,0,0,0,0,0,0,0,0,0,0,0,0,0,0,
 1,1,1,1,1,1,1,1,1,1,1,1,1,1,
 2,2,2,2,2,2,2,2,2,2,2,2,2,
 3,3,3,3,3,3,3,3,3,3,3,3,
 4,4,4,4,4,4,4,4,4,4,4,
 5,5,5,5,5,5,5,5,5,5,
 6,6,6,6,6,6,6,6,6,
 7,7,7,7,7,7,7,7,
 8,8,8,8,8,8,8,
 9,9,9,9,9,9,
 10,10,10,10,10,
 11,11,11,11,
 12,12,12,
 13,13,
 14};
__constant__ int c_tri_c[120] = {
 1,2,3,4,5,6,7,8,9,10,11,12,13,14,15,
 2,3,4,5,6,7,8,9,10,11,12,13,14,15,
 3,4,5,6,7,8,9,10,11,12,13,14,15,
 4,5,6,7,8,9,10,11,12,13,14,15,
 5,6,7,8,9,10,11,12,13,14,15,
 6,7,8,9,10,11,12,13,14,15,
 7,8,9,10,11,12,13,14,15,
 8,9,10,11,12,13,14,15,
 9,10,11,12,13,14,15,
 10,11,12,13,14,15,
 11,12,13,14,15,
 12,13,14,15,
 13,14,15,
 14,15,
 15};

__device__ __forceinline__ float ftanh(float x) {
    float y;
    asm("tanh.approx.f32 %0, %1;" : "=f"(y) : "f"(x));
    return y;
}

// ---------------- kernel A: tiled GEMM  C[512 x 512] = X @ [Wq;Wk;W1]^T ----
__global__ void __launch_bounds__(256)
prep_kernel(const float* __restrict__ xl,
            const float* __restrict__ Wq, const float* __restrict__ bq,
            const float* __restrict__ Wk, const float* __restrict__ bk,
            const float* __restrict__ W1)
{
    __shared__ __align__(16) float Xs[64*64];
    __shared__ __align__(16) float Wt[64*68];

    int bx = blockIdx.x, by = blockIdx.y;
    int t  = threadIdx.x;
    int tx = t & 15, ty = t >> 4;

    const float* src;
    if      (by < 2) src = Wq + (by    )*64*DL;
    else if (by < 4) src = Wk + (by - 2)*64*DL;
    else             src = W1 + (by - 4)*64*DL;

    float acc[4][4];
    #pragma unroll
    for (int i = 0; i < 4; i++)
        #pragma unroll
        for (int j = 0; j < 4; j++) acc[i][j] = 0.f;

    for (int k0 = 0; k0 < DL; k0 += 64) {
        __syncthreads();
        #pragma unroll
        for (int s = 0; s < 16; s++) {
            int idx = t + 256*s;
            int r = idx >> 6, k = idx & 63;
            Xs[r*64 + k] = xl[(bx*64 + r)*DL + k0 + k];
            Wt[k*68 + r] = src[r*DL + k0 + k];
        }
        __syncthreads();

        #pragma unroll 8
        for (int k = 0; k < 64; k++) {
            float4 bv = *(const float4*)&Wt[k*68 + tx*4];
            #pragma unroll
            for (int i = 0; i < 4; i++) {
                float a = Xs[(ty*4 + i)*64 + k];
                acc[i][0] = fmaf(a, bv.x, acc[i][0]);
                acc[i][1] = fmaf(a, bv.y, acc[i][1]);
                acc[i][2] = fmaf(a, bv.z, acc[i][2]);
                acc[i][3] = fmaf(a, bv.w, acc[i][3]);
            }
        }
    }

    #pragma unroll
    for (int i = 0; i < 4; i++) {
        int rowg = bx*64 + ty*4 + i;
        int c0   = tx*4;
        if (by < 2) {
            int col = by*64 + c0;
            *(float4*)&g_Q[rowg*DL + col] =
                make_float4(acc[i][0]+bq[col], acc[i][1]+bq[col+1],
                            acc[i][2]+bq[col+2], acc[i][3]+bq[col+3]);
        } else if (by < 4) {
            int col = (by-2)*64 + c0;
            *(float4*)&g_K[rowg*DL + col] =
                make_float4(acc[i][0]+bk[col], acc[i][1]+bk[col+1],
                            acc[i][2]+bk[col+2], acc[i][3]+bk[col+3]);
        } else {
            int col = (by-4)*64 + c0;
            *(float4*)&g_U[rowg*256 + col] =
                make_float4(acc[i][0], acc[i][1], acc[i][2], acc[i][3]);
        }
    }
}

// ---------------- kernel B: attention softmax (+ zero g_settled) -----------
#define AT_QS 0
#define AT_KT (AT_QS + 32*128)
#define AT_S  (AT_KT + 128*132)
#define AT_FLOATS (AT_S + 32*132)
#define AT_BYTES  (AT_FLOATS*4)

__global__ void __launch_bounds__(256)
attn_kernel()
{
    extern __shared__ float sm[];
    float* Qs = sm + AT_QS;
    float* Kt = sm + AT_KT;
    float* S  = sm + AT_S;

    int b  = blockIdx.x >> 2;
    int jt = (blockIdx.x & 3) * 32;
    int t  = threadIdx.x;
    int tx = t & 15, ty = t >> 4;

    for (int z = t; z < 512; z += 256) g_settled[blockIdx.x*512 + z] = 0.f;

    for (int idx = t; idx < 32*128; idx += 256) {
        int j = idx >> 7, k = idx & 127;
        Qs[j*128 + k] = g_Q[(b*SEQ + jt + j)*DL + k];
    }
    for (int idx = t; idx < 128*128; idx += 256) {
        int i = idx >> 7, k = idx & 127;
        Kt[k*132 + i] = g_K[(b*SEQ + i)*DL + k];
    }
    __syncthreads();

    float acc[2][8];
    #pragma unroll
    for (int i = 0; i < 2; i++)
        #pragma unroll
        for (int j = 0; j < 8; j++) acc[i][j] = 0.f;

    int j0 = ty*2, i0 = tx*8;
    #pragma unroll 4
    for (int k = 0; k < 128; k++) {
        float q0 = Qs[(j0  )*128 + k];
        float q1 = Qs[(j0+1)*128 + k];
        float4 k0v = *(const float4*)&Kt[k*132 + i0];
        float4 k1v = *(const float4*)&Kt[k*132 + i0 + 4];
        acc[0][0]=fmaf(q0,k0v.x,acc[0][0]); acc[0][1]=fmaf(q0,k0v.y,acc[0][1]);
        acc[0][2]=fmaf(q0,k0v.z,acc[0][2]); acc[0][3]=fmaf(q0,k0v.w,acc[0][3]);
        acc[0][4]=fmaf(q0,k1v.x,acc[0][4]); acc[0][5]=fmaf(q0,k1v.y,acc[0][5]);
        acc[0][6]=fmaf(q0,k1v.z,acc[0][6]); acc[0][7]=fmaf(q0,k1v.w,acc[0][7]);
        acc[1][0]=fmaf(q1,k0v.x,acc[1][0]); acc[1][1]=fmaf(q1,k0v.y,acc[1][1]);
        acc[1][2]=fmaf(q1,k0v.z,acc[1][2]); acc[1][3]=fmaf(q1,k0v.w,acc[1][3]);
        acc[1][4]=fmaf(q1,k1v.x,acc[1][4]); acc[1][5]=fmaf(q1,k1v.y,acc[1][5]);
        acc[1][6]=fmaf(q1,k1v.z,acc[1][6]); acc[1][7]=fmaf(q1,k1v.w,acc[1][7]);
    }
    const float sc = 0.08838834764831845f;
    #pragma unroll
    for (int i = 0; i < 2; i++) {
        *(float4*)&S[(j0+i)*132 + i0] =
            make_float4(acc[i][0]*sc, acc[i][1]*sc, acc[i][2]*sc, acc[i][3]*sc);
        *(float4*)&S[(j0+i)*132 + i0 + 4] =
            make_float4(acc[i][4]*sc, acc[i][5]*sc, acc[i][6]*sc, acc[i][7]*sc);
    }
    __syncthreads();

    int w = t >> 5, lane = t & 31;
    for (int q = 0; q < 4; q++) {
        int r = w*4 + q;
        float v0 = S[r*132 + lane      ];
        float v1 = S[r*132 + lane + 32 ];
        float v2 = S[r*132 + lane + 64 ];
        float v3 = S[r*132 + lane + 96 ];
        float mx = fmaxf(fmaxf(v0,v1), fmaxf(v2,v3));
        #pragma unroll
        for (int off = 16; off; off >>= 1)
            mx = fmaxf(mx, __shfl_xor_sync(0xffffffffu, mx, off));
        float e0 = expf(v0-mx), e1 = expf(v1-mx), e2 = expf(v2-mx), e3 = expf(v3-mx);
        float sum = e0+e1+e2+e3;
        #pragma unroll
        for (int off = 16; off; off >>= 1)
            sum += __shfl_xor_sync(0xffffffffu, sum, off);
        float inv = 1.f/sum;
        float* dst = g_attn + (b*SEQ + jt + r)*SEQ;
        dst[lane     ] = e0*inv;
        dst[lane + 32] = e1*inv;
        dst[lane + 64] = e2*inv;
        dst[lane + 96] = e3*inv;
    }
}

// ---------------- kernel C: pairwise MLP GEMM -> g_lie  (FFMA2) ------------
__global__ void __launch_bounds__(256, 2)
pair_kernel(const float* __restrict__ b1, const float* __restrict__ W2,
            const float* __restrict__ b2)
{
    __shared__ __align__(16) float Ujb[256];
    __shared__ __align__(16) float As[32*132];   // [kk][i]
    __shared__ __align__(16) float Bs[32*132];   // [kk][c]

    int row = blockIdx.x;          // b*128 + j
    int b   = row >> 7;
    int t   = threadIdx.x;

    Ujb[t] = g_U[row*256 + t] + b1[t];

    int i0 = (t & 15) * 8;
    int c0 = (t >> 4) * 8;

    unsigned bsBase = (unsigned)__cvta_generic_to_shared(Bs) + c0*4;

    u64 acc2[8][4];
    #pragma unroll
    for (int i = 0; i < 8; i++)
        #pragma unroll
        for (int j = 0; j < 4; j++) acc2[i][j] = 0ull;

    for (int k0 = 0; k0 < 256; k0 += 32) {
        __syncthreads();
        #pragma unroll
        for (int s = 0; s < 16; s++) {
            int idx = t + 256*s;          // 4096
            int i = idx >> 5, kk = idx & 31;
            float u = g_U[(b*SEQ + i)*256 + k0 + kk];
            As[kk*132 + i] = ftanh(Ujb[k0 + kk] - u);
        }
        #pragma unroll
        for (int s = 0; s < 15; s++) {
            int idx = t + 256*s;          // 3840
            int c = idx >> 5, kk = idx & 31;
            Bs[kk*132 + c] = W2[c*256 + k0 + kk];
        }
        { int c = 120 + (t >> 5), kk = t & 31; Bs[kk*132 + c] = 0.f; }
        __syncthreads();

        #pragma unroll
        for (int kk = 0; kk < 32; kk++) {
            unsigned bAddr = bsBase + kk*132*4;
            float4 aA = *(const float4*)&As[kk*132 + i0];
            float4 aB = *(const float4*)&As[kk*132 + i0 + 4];
            u64 b01, b23, b45, b67;
            LDS_2x64(b01, b23, bAddr);
            LDS_2x64(b45, b67, bAddr + 16);
            float av[8] = {aA.x,aA.y,aA.z,aA.w,aB.x,aB.y,aB.z,aB.w};
            #pragma unroll
            for (int i = 0; i < 8; i++) {
                u64 ad; DUP2(ad, av[i]);
                FMA2(acc2[i][0], ad, b01, acc2[i][0]);
                FMA2(acc2[i][1], ad, b23, acc2[i][1]);
                FMA2(acc2[i][2], ad, b45, acc2[i][2]);
                FMA2(acc2[i][3], ad, b67, acc2[i][3]);
            }
        }
    }

    if (c0 < SO) {
        float4 bb0 = *(const float4*)&b2[c0];
        float4 bb1 = *(const float4*)&b2[c0 + 4];
        float bb[8] = {bb0.x,bb0.y,bb0.z,bb0.w,bb1.x,bb1.y,bb1.z,bb1.w};
        #pragma unroll
        for (int ii = 0; ii < 8; ii++) {
            float v[8];
            #pragma unroll
            for (int jp = 0; jp < 4; jp++) {
                unsigned lo, hi;
                UNPK2(lo, hi, acc2[ii][jp]);
                v[2*jp]   = __uint_as_float(lo) + bb[2*jp];
                v[2*jp+1] = __uint_as_float(hi) + bb[2*jp+1];
            }
            size_t p = (size_t)row*SEQ + (i0 + ii);
            float* dst = g_lie + p*SO + c0;
            *(float4*)dst     = make_float4(v[0],v[1],v[2],v[3]);
            *(float4*)(dst+4) = make_float4(v[4],v[5],v[6],v[7]);
        }
    }
}

// ------ paired warp 16x16 matmul: 2-row x 4-col tiles, row-split (r, r+8) --
// Lane owns rows r=lane>>2 and r+8, cols c0..c0+3 with c0=(lane&3)*4.
// LDS per matmul per pair: 16 A-preload + 32 B = 48 LDS.128 (all conflict-free).
__device__ __forceinline__ void wmm_pair2(
    const float* __restrict__ A0, const float* __restrict__ B0,
    const float* __restrict__ A1, const float* __restrict__ B1,
    float R0[2][4], float R1[2][4], int r, int c0)
{
    #pragma unroll
    for (int j = 0; j < 4; j++) {
        R0[0][j]=0.f; R0[1][j]=0.f; R1[0][j]=0.f; R1[1][j]=0.f;
    }
    #pragma unroll
    for (int h = 0; h < 2; h++) {
        float a0lo[8], a0hi[8], a1lo[8], a1hi[8];
        #pragma unroll
        for (int q = 0; q < 2; q++) {
            float4 v;
            v = *(const float4*)&A0[(r  )*20 + 8*h + 4*q];
            a0lo[4*q]=v.x; a0lo[4*q+1]=v.y; a0lo[4*q+2]=v.z; a0lo[4*q+3]=v.w;
            v = *(const float4*)&A0[(r+8)*20 + 8*h + 4*q];
            a0hi[4*q]=v.x; a0hi[4*q+1]=v.y; a0hi[4*q+2]=v.z; a0hi[4*q+3]=v.w;
            v = *(const float4*)&A1[(r  )*20 + 8*h + 4*q];
            a1lo[4*q]=v.x; a1lo[4*q+1]=v.y; a1lo[4*q+2]=v.z; a1lo[4*q+3]=v.w;
            v = *(const float4*)&A1[(r+8)*20 + 8*h + 4*q];
            a1hi[4*q]=v.x; a1hi[4*q+1]=v.y; a1hi[4*q+2]=v.z; a1hi[4*q+3]=v.w;
        }
        #pragma unroll
        for (int kk = 0; kk < 8; kk++) {
            int k = 8*h + kk;
            float4 b0 = *(const float4*)&B0[k*20 + c0];
            float4 b1 = *(const float4*)&B1[k*20 + c0];
            R0[0][0]=fmaf(a0lo[kk],b0.x,R0[0][0]); R0[0][1]=fmaf(a0lo[kk],b0.y,R0[0][1]);
            R0[0][2]=fmaf(a0lo[kk],b0.z,R0[0][2]); R0[0][3]=fmaf(a0lo[kk],b0.w,R0[0][3]);
            R0[1][0]=fmaf(a0hi[kk],b0.x,R0[1][0]); R0[1][1]=fmaf(a0hi[kk],b0.y,R0[1][1]);
            R0[1][2]=fmaf(a0hi[kk],b0.z,R0[1][2]); R0[1][3]=fmaf(a0hi[kk],b0.w,R0[1][3]);
            R1[0][0]=fmaf(a1lo[kk],b1.x,R1[0][0]); R1[0][1]=fmaf(a1lo[kk],b1.y,R1[0][1]);
            R1[0][2]=fmaf(a1lo[kk],b1.z,R1[0][2]); R1[0][3]=fmaf(a1lo[kk],b1.w,R1[0][3]);
            R1[1][0]=fmaf(a1hi[kk],b1.x,R1[1][0]); R1[1][1]=fmaf(a1hi[kk],b1.y,R1[1][1]);
            R1[1][2]=fmaf(a1hi[kk],b1.z,R1[1][2]); R1[1][3]=fmaf(a1hi[kk],b1.w,R1[1][3]);
        }
    }
}

__device__ __forceinline__ void st2(float* __restrict__ C, const float R[2][4],
                                    int r, int c0)
{
    *(float4*)&C[(r  )*20 + c0] = make_float4(R[0][0],R[0][1],R[0][2],R[0][3]);
    *(float4*)&C[(r+8)*20 + c0] = make_float4(R[1][0],R[1][1],R[1][2],R[1][3]);
}

// ---------------- kernel D: expm + aggregate (2 matrices / warp) -----------
#define EXPM_BLOCKS 592    // 4 blocks/SM * 148 SMs

__global__ void __launch_bounds__(128, 4)
expm_kernel(const float* __restrict__ xm_g, float* __restrict__ Tout)
{
    __shared__ __align__(16) float mm[4*2*4*320];   // 40 KB
    int t = threadIdx.x, lane = t & 31, w = t >> 5;
    float* M0  = mm + w*(2*4*320);
    float* A0b = M0;        float* A20 = M0 + 320;
    float* A30 = M0 + 640;  float* T0  = M0 + 960;
    float* M1  = M0 + 1280;
    float* A1b = M1;        float* A21 = M1 + 320;
    float* A31 = M1 + 640;  float* T1  = M1 + 960;

    int r  = lane >> 2;          // rows r and r+8
    int c0 = (lane & 3) * 4;     // cols c0..c0+3

    const float c3=1.f/6.f, c4=1.f/24.f, c5=1.f/120.f;
    const float c6=1.f/720.f, c7=1.f/5040.f, c8=1.f/40320.f, c9=1.f/362880.f;

    int gw = blockIdx.x*4 + w;            // global warp id
    int gstride = EXPM_BLOCKS*4;

    for (int pp = gw; pp < 32768; pp += gstride) {
        int p0 = pp*2, p1 = p0 + 1;
        int row = p0 >> 7;                // b*128 + j  (same for both)
        int i0  = p0 & 127, i1 = i0 + 1;
        int b   = row >> 7;

        // ---- scatter lie -> skew (both matrices) ----
        const float* lr0 = g_lie + (size_t)p0*SO;
        const float* lr1 = g_lie + (size_t)p1*SO;
        if (lane < 16) { A0b[lane*20 + lane] = 0.f; A1b[lane*20 + lane] = 0.f; }
        #pragma unroll
        for (int q = 0; q < 4; q++) {
            int l = lane + 32*q;
            if (l < SO) {
                int rI = c_tri_r[l], cI = c_tri_c[l];
                float v0 = lr0[l], v1 = lr1[l];
                A0b[rI*20 + cI] =  v0;  A0b[cI*20 + rI] = -v0;
                A1b[rI*20 + cI] =  v1;  A1b[cI*20 + rI] = -v1;
            }
        }
        __syncwarp();

        // ---- load tiles, joint inf-norm -> shared scaling exponent ----
        float tA0[2][4], tA1[2][4];
        {
            float4 v;
            v = *(const float4*)&A0b[(r  )*20 + c0];
            tA0[0][0]=v.x; tA0[0][1]=v.y; tA0[0][2]=v.z; tA0[0][3]=v.w;
            v = *(const float4*)&A0b[(r+8)*20 + c0];
            tA0[1][0]=v.x; tA0[1][1]=v.y; tA0[1][2]=v.z; tA0[1][3]=v.w;
            v = *(const float4*)&A1b[(r  )*20 + c0];
            tA1[0][0]=v.x; tA1[0][1]=v.y; tA1[0][2]=v.z; tA1[0][3]=v.w;
            v = *(const float4*)&A1b[(r+8)*20 + c0];
            tA1[1][0]=v.x; tA1[1][1]=v.y; tA1[1][2]=v.z; tA1[1][3]=v.w;
        }
        float s0lo = fabsf(tA0[0][0])+fabsf(tA0[0][1])+fabsf(tA0[0][2])+fabsf(tA0[0][3]);
        float s0hi = fabsf(tA0[1][0])+fabsf(tA0[1][1])+fabsf(tA0[1][2])+fabsf(tA0[1][3]);
        float s1lo = fabsf(tA1[0][0])+fabsf(tA1[0][1])+fabsf(tA1[0][2])+fabsf(tA1[0][3]);
        float s1hi = fabsf(tA1[1][0])+fabsf(tA1[1][1])+fabsf(tA1[1][2])+fabsf(tA1[1][3]);
        // reduce over cg (lane bits 0..1)
        #pragma unroll
        for (int off = 1; off <= 2; off <<= 1) {
            s0lo += __shfl_xor_sync(0xffffffffu, s0lo, off);
            s0hi += __shfl_xor_sync(0xffffffffu, s0hi, off);
            s1lo += __shfl_xor_sync(0xffffffffu, s1lo, off);
            s1hi += __shfl_xor_sync(0xffffffffu, s1hi, off);
        }
        float mx = fmaxf(fmaxf(s0lo, s0hi), fmaxf(s1lo, s1hi));
        #pragma unroll
        for (int off = 4; off <= 16; off <<= 1)
            mx = fmaxf(mx, __shfl_xor_sync(0xffffffffu, mx, off));
        int sct = 0;
        if (mx > 1.f) { sct = (int)ceilf(log2f(mx)); if (sct > 12) sct = 12; }
        float scale = __uint_as_float((uint32_t)(127 - sct) << 23);

        #pragma unroll
        for (int i = 0; i < 2; i++)
            #pragma unroll
            for (int j = 0; j < 4; j++) {
                tA0[i][j] *= scale;
                tA1[i][j] *= scale;
            }
        st2(A0b, tA0, r, c0);
        st2(A1b, tA1, r, c0);
        __syncwarp();

        float R0[2][4], R1[2][4];
        float tB0[2][4], tB1[2][4];     // A^2 tiles

        // ---- A2 = A*A ----
        wmm_pair2(A0b, A0b, A1b, A1b, R0, R1, r, c0);
        #pragma unroll
        for (int i = 0; i < 2; i++)
            #pragma unroll
            for (int j = 0; j < 4; j++) { tB0[i][j] = R0[i][j]; tB1[i][j] = R1[i][j]; }
        st2(A20, R0, r, c0); st2(A21, R1, r, c0);
        __syncwarp();

        // ---- A3 = A2*A ----
        wmm_pair2(A20, A0b, A21, A1b, R0, R1, r, c0);
        st2(A30, R0, r, c0); st2(A31, R1, r, c0);

        // ---- B2 = c6 I + c7 A + c8 A2 + c9 A3 (in place on R) -> T ----
        #pragma unroll
        for (int i = 0; i < 2; i++)
            #pragma unroll
            for (int j = 0; j < 4; j++) {
                int rowI = r + 8*i;
                float v0 = fmaf(c7, tA0[i][j], fmaf(c8, tB0[i][j], c9 * R0[i][j]));
                float v1 = fmaf(c7, tA1[i][j], fmaf(c8, tB1[i][j], c9 * R1[i][j]));
                if (rowI == c0 + j) { v0 += c6; v1 += c6; }
                R0[i][j] = v0; R1[i][j] = v1;
            }
        st2(T0, R0, r, c0); st2(T1, R1, r, c0);
        __syncwarp();

        // ---- T = A3*B2 + (c3 I + c4 A + c5 A2) ----
        wmm_pair2(A30, T0, A31, T1, R0, R1, r, c0);
        __syncwarp();
        #pragma unroll
        for (int i = 0; i < 2; i++)
            #pragma unroll
            for (int j = 0; j < 4; j++) {
                int rowI = r + 8*i;
                R0[i][j] += fmaf(c4, tA0[i][j], c5 * tB0[i][j]);
                R1[i][j] += fmaf(c4, tA1[i][j], c5 * tB1[i][j]);
                if (rowI == c0 + j) { R0[i][j] += c3; R1[i][j] += c3; }
            }
        st2(T0, R0, r, c0); st2(T1, R1, r, c0);
        __syncwarp();

        // ---- R = A3*T + (I + A + A2/2) ----
        wmm_pair2(A30, T0, A31, T1, R0, R1, r, c0);
        #pragma unroll
        for (int i = 0; i < 2; i++)
            #pragma unroll
            for (int j = 0; j < 4; j++) {
                int rowI = r + 8*i;
                R0[i][j] += fmaf(0.5f, tB0[i][j], tA0[i][j]);
                R1[i][j] += fmaf(0.5f, tB1[i][j], tA1[i][j]);
                if (rowI == c0 + j) { R0[i][j] += 1.f; R1[i][j] += 1.f; }
            }

        // ---- squarings (shared sct for the pair) ----
        for (int q = 0; q < sct; q++) {
            __syncwarp();
            st2(T0, R0, r, c0); st2(T1, R1, r, c0);
            __syncwarp();
            wmm_pair2(T0, T0, T1, T1, R0, R1, r, c0);
        }

        // ---- write T_all (coalesced: offset = 4*lane) ----
        float* d0 = Tout + (size_t)p0*256;
        float* d1 = Tout + (size_t)p1*256;
        *(float4*)&d0[(r  )*16 + c0] = make_float4(R0[0][0],R0[0][1],R0[0][2],R0[0][3]);
        *(float4*)&d0[(r+8)*16 + c0] = make_float4(R0[1][0],R0[1][1],R0[1][2],R0[1][3]);
        *(float4*)&d1[(r  )*16 + c0] = make_float4(R1[0][0],R1[0][1],R1[0][2],R1[0][3]);
        *(float4*)&d1[(r+8)*16 + c0] = make_float4(R1[1][0],R1[1][1],R1[1][2],R1[1][3]);

        // ---- transported & settled ----
        float4 xv0 = *(const float4*)&xm_g[((size_t)b*SEQ + i0)*DM + c0];
        float4 xv1 = *(const float4*)&xm_g[((size_t)b*SEQ + i1)*DM + c0];
        float plo0 = R0[0][0]*xv0.x + R0[0][1]*xv0.y + R0[0][2]*xv0.z + R0[0][3]*xv0.w;
        float phi0 = R0[1][0]*xv0.x + R0[1][1]*xv0.y + R0[1][2]*xv0.z + R0[1][3]*xv0.w;
        float plo1 = R1[0][0]*xv1.x + R1[0][1]*xv1.y + R1[0][2]*xv1.z + R1[0][3]*xv1.w;
        float phi1 = R1[1][0]*xv1.x + R1[1][1]*xv1.y + R1[1][2]*xv1.z + R1[1][3]*xv1.w;
        #pragma unroll
        for (int off = 1; off <= 2; off <<= 1) {
            plo0 += __shfl_xor_sync(0xffffffffu, plo0, off);
            phi0 += __shfl_xor_sync(0xffffffffu, phi0, off);
            plo1 += __shfl_xor_sync(0xffffffffu, plo1, off);
            phi1 += __shfl_xor_sync(0xffffffffu, phi1, off);
        }
        if ((lane & 3) == 0) {
            float w0 = g_attn[row*SEQ + i0];
            float w1 = g_attn[row*SEQ + i1];
            atomicAdd(&g_settled[row*DM + r    ], fmaf(w0, plo0, w1 * plo1));
            atomicAdd(&g_settled[row*DM + r + 8], fmaf(w0, phi0, w1 * phi1));
        }
        __syncwarp();
    }
}

// ---------------- kernel E: out projection ---------------------------------
__global__ void __launch_bounds__(256)
out_kernel(const float* __restrict__ Wo, const float* __restrict__ bo,
           float* __restrict__ out)
{
    int gid = blockIdx.x*256 + threadIdx.x;    // 8192
    int row = gid >> 4, d = gid & 15;
    float acc = bo[d];
    #pragma unroll
    for (int e = 0; e < DM; e++)
        acc = fmaf(Wo[d*DM + e], g_settled[row*DM + e], acc);
    out[gid] = acc;
}

// ---------------- launch ----------------------------------------------------
extern "C" void kernel_launch(void* const* d_in, const int* in_sizes, int n_in,
                              void* d_out, int out_size)
{
    const float* xl  = (const float*)d_in[0];
    const float* xmm = (const float*)d_in[1];
    const float* Wq  = (const float*)d_in[2];
    const float* bq  = (const float*)d_in[3];
    const float* Wk  = (const float*)d_in[4];
    const float* bk  = (const float*)d_in[5];
    const float* W1  = (const float*)d_in[6];
    const float* b1  = (const float*)d_in[7];
    const float* W2  = (const float*)d_in[8];
    const float* b2  = (const float*)d_in[9];
    const float* Wo  = (const float*)d_in[10];
    const float* bo  = (const float*)d_in[11];

    float* out  = (float*)d_out;
    float* Tout = out + NB*SEQ*DM;      // T_all follows out

    static bool attr_set = false;
    if (!attr_set) {
        cudaFuncSetAttribute(attn_kernel, cudaFuncAttributeMaxDynamicSharedMemorySize, AT_BYTES);
        attr_set = true;
    }

    prep_kernel<<<dim3(8,8), 256>>>(xl, Wq, bq, Wk, bk, W1);
    attn_kernel<<<16, 256, AT_BYTES>>>();
    pair_kernel<<<ROWS, 256>>>(b1, W2, b2);
    expm_kernel<<<EXPM_BLOCKS, 128>>>(xmm, Tout);
    out_kernel<<<32, 256>>>(Wo, bo, out);
}

// round 9
// speedup vs baseline: 1.3211x; 1.2189x over previous
#include <cuda_runtime.h>
#include <math.h>
#include <stdint.h>

#define NB 4
#define SEQ 128
#define DL 128
#define DM 16
#define SO 120
#define ROWS (NB*SEQ)        // 512

typedef unsigned long long u64;

// packed fp32x2 FMA (sm_100+)
#define FMA2(d,a,b,c) asm("fma.rn.f32x2 %0, %1, %2, %3;" : "=l"(d) : "l"(a), "l"(b), "l"(c))
#define DUP2(d,s)     asm("mov.b64 %0, {%1, %1};" : "=l"(d) : "r"(__float_as_uint(s)))
#define UNPK2(lo,hi,p) asm("mov.b64 {%0, %1}, %2;" : "=r"(lo), "=r"(hi) : "l"(p))
#define LDS_2x64(p0,p1,addr) asm volatile("ld.shared.v2.b64 {%0, %1}, [%2];" : "=l"(p0), "=l"(p1) : "r"(addr))

// ---------------- scratch ----------------------------------------------------
__device__ float g_Q[ROWS*DL];
__device__ float g_K[ROWS*DL];
__device__ float g_U[ROWS*256];
__device__ float g_attn[NB*SEQ*SEQ];
__device__ float g_lie[(size_t)NB*SEQ*SEQ*SO];   // 31.5 MB
__device__ float g_settled[ROWS*DM];

__constant__ int c_tri_r[120] = {
 0,0,0,0,0,0,0,0,0,0,0,0,0,0,0,
 1,1,1,1,1,1,1,1,1,1,1,1,1,1,
 2,2,2,2,2,2,2,2,2,2,2,2,2,
 3,3,3,3,3,3,3,3,3,3,3,3,
 4,4,4,4,4,4,4,4,4,4,4,
 5,5,5,5,5,5,5,5,5,5,
 6,6,6,6,6,6,6,6,6,
 7,7,7,7,7,7,7,7,
 8,8,8,8,8,8,8,
 9,9,9,9,9,9,
 10,10,10,10,10,
 11,11,11,11,
 12,12,12,
 13,13,
 14};
__constant__ int c_tri_c[120] = {
 1,2,3,4,5,6,7,8,9,10,11,12,13,14,15,
 2,3,4,5,6,7,8,9,10,11,12,13,14,15,
 3,4,5,6,7,8,9,10,11,12,13,14,15,
 4,5,6,7,8,9,10,11,12,13,14,15,
 5,6,7,8,9,10,11,12,13,14,15,
 6,7,8,9,10,11,12,13,14,15,
 7,8,9,10,11,12,13,14,15,
 8,9,10,11,12,13,14,15,
 9,10,11,12,13,14,15,
 10,11,12,13,14,15,
 11,12,13,14,15,
 12,13,14,15,
 13,14,15,
 14,15,
 15};

__device__ __forceinline__ float ftanh(float x) {
    float y;
    asm("tanh.approx.f32 %0, %1;" : "=f"(y) : "f"(x));
    return y;
}

// ---------------- kernel A: tiled GEMM  C[512 x 512] = X @ [Wq;Wk;W1]^T ----
__global__ void __launch_bounds__(256)
prep_kernel(const float* __restrict__ xl,
            const float* __restrict__ Wq, const float* __restrict__ bq,
            const float* __restrict__ Wk, const float* __restrict__ bk,
            const float* __restrict__ W1)
{
    __shared__ __align__(16) float Xs[64*64];
    __shared__ __align__(16) float Wt[64*68];

    int bx = blockIdx.x, by = blockIdx.y;
    int t  = threadIdx.x;
    int tx = t & 15, ty = t >> 4;

    const float* src;
    if      (by < 2) src = Wq + (by    )*64*DL;
    else if (by < 4) src = Wk + (by - 2)*64*DL;
    else             src = W1 + (by - 4)*64*DL;

    float acc[4][4];
    #pragma unroll
    for (int i = 0; i < 4; i++)
        #pragma unroll
        for (int j = 0; j < 4; j++) acc[i][j] = 0.f;

    for (int k0 = 0; k0 < DL; k0 += 64) {
        __syncthreads();
        #pragma unroll
        for (int s = 0; s < 16; s++) {
            int idx = t + 256*s;
            int r = idx >> 6, k = idx & 63;
            Xs[r*64 + k] = xl[(bx*64 + r)*DL + k0 + k];
            Wt[k*68 + r] = src[r*DL + k0 + k];
        }
        __syncthreads();

        #pragma unroll 8
        for (int k = 0; k < 64; k++) {
            float4 bv = *(const float4*)&Wt[k*68 + tx*4];
            #pragma unroll
            for (int i = 0; i < 4; i++) {
                float a = Xs[(ty*4 + i)*64 + k];
                acc[i][0] = fmaf(a, bv.x, acc[i][0]);
                acc[i][1] = fmaf(a, bv.y, acc[i][1]);
                acc[i][2] = fmaf(a, bv.z, acc[i][2]);
                acc[i][3] = fmaf(a, bv.w, acc[i][3]);
            }
        }
    }

    #pragma unroll
    for (int i = 0; i < 4; i++) {
        int rowg = bx*64 + ty*4 + i;
        int c0   = tx*4;
        if (by < 2) {
            int col = by*64 + c0;
            *(float4*)&g_Q[rowg*DL + col] =
                make_float4(acc[i][0]+bq[col], acc[i][1]+bq[col+1],
                            acc[i][2]+bq[col+2], acc[i][3]+bq[col+3]);
        } else if (by < 4) {
            int col = (by-2)*64 + c0;
            *(float4*)&g_K[rowg*DL + col] =
                make_float4(acc[i][0]+bk[col], acc[i][1]+bk[col+1],
                            acc[i][2]+bk[col+2], acc[i][3]+bk[col+3]);
        } else {
            int col = (by-4)*64 + c0;
            *(float4*)&g_U[rowg*256 + col] =
                make_float4(acc[i][0], acc[i][1], acc[i][2], acc[i][3]);
        }
    }
}

// ---------------- kernel B: attention softmax (+ zero g_settled) -----------
#define AT_QS 0
#define AT_KT (AT_QS + 32*128)
#define AT_S  (AT_KT + 128*132)
#define AT_FLOATS (AT_S + 32*132)
#define AT_BYTES  (AT_FLOATS*4)

__global__ void __launch_bounds__(256)
attn_kernel()
{
    extern __shared__ float sm[];
    float* Qs = sm + AT_QS;
    float* Kt = sm + AT_KT;
    float* S  = sm + AT_S;

    int b  = blockIdx.x >> 2;
    int jt = (blockIdx.x & 3) * 32;
    int t  = threadIdx.x;
    int tx = t & 15, ty = t >> 4;

    for (int z = t; z < 512; z += 256) g_settled[blockIdx.x*512 + z] = 0.f;

    for (int idx = t; idx < 32*128; idx += 256) {
        int j = idx >> 7, k = idx & 127;
        Qs[j*128 + k] = g_Q[(b*SEQ + jt + j)*DL + k];
    }
    for (int idx = t; idx < 128*128; idx += 256) {
        int i = idx >> 7, k = idx & 127;
        Kt[k*132 + i] = g_K[(b*SEQ + i)*DL + k];
    }
    __syncthreads();

    float acc[2][8];
    #pragma unroll
    for (int i = 0; i < 2; i++)
        #pragma unroll
        for (int j = 0; j < 8; j++) acc[i][j] = 0.f;

    int j0 = ty*2, i0 = tx*8;
    #pragma unroll 4
    for (int k = 0; k < 128; k++) {
        float q0 = Qs[(j0  )*128 + k];
        float q1 = Qs[(j0+1)*128 + k];
        float4 k0v = *(const float4*)&Kt[k*132 + i0];
        float4 k1v = *(const float4*)&Kt[k*132 + i0 + 4];
        acc[0][0]=fmaf(q0,k0v.x,acc[0][0]); acc[0][1]=fmaf(q0,k0v.y,acc[0][1]);
        acc[0][2]=fmaf(q0,k0v.z,acc[0][2]); acc[0][3]=fmaf(q0,k0v.w,acc[0][3]);
        acc[0][4]=fmaf(q0,k1v.x,acc[0][4]); acc[0][5]=fmaf(q0,k1v.y,acc[0][5]);
        acc[0][6]=fmaf(q0,k1v.z,acc[0][6]); acc[0][7]=fmaf(q0,k1v.w,acc[0][7]);
        acc[1][0]=fmaf(q1,k0v.x,acc[1][0]); acc[1][1]=fmaf(q1,k0v.y,acc[1][1]);
        acc[1][2]=fmaf(q1,k0v.z,acc[1][2]); acc[1][3]=fmaf(q1,k0v.w,acc[1][3]);
        acc[1][4]=fmaf(q1,k1v.x,acc[1][4]); acc[1][5]=fmaf(q1,k1v.y,acc[1][5]);
        acc[1][6]=fmaf(q1,k1v.z,acc[1][6]); acc[1][7]=fmaf(q1,k1v.w,acc[1][7]);
    }
    const float sc = 0.08838834764831845f;
    #pragma unroll
    for (int i = 0; i < 2; i++) {
        *(float4*)&S[(j0+i)*132 + i0] =
            make_float4(acc[i][0]*sc, acc[i][1]*sc, acc[i][2]*sc, acc[i][3]*sc);
        *(float4*)&S[(j0+i)*132 + i0 + 4] =
            make_float4(acc[i][4]*sc, acc[i][5]*sc, acc[i][6]*sc, acc[i][7]*sc);
    }
    __syncthreads();

    int w = t >> 5, lane = t & 31;
    for (int q = 0; q < 4; q++) {
        int r = w*4 + q;
        float v0 = S[r*132 + lane      ];
        float v1 = S[r*132 + lane + 32 ];
        float v2 = S[r*132 + lane + 64 ];
        float v3 = S[r*132 + lane + 96 ];
        float mx = fmaxf(fmaxf(v0,v1), fmaxf(v2,v3));
        #pragma unroll
        for (int off = 16; off; off >>= 1)
            mx = fmaxf(mx, __shfl_xor_sync(0xffffffffu, mx, off));
        float e0 = expf(v0-mx), e1 = expf(v1-mx), e2 = expf(v2-mx), e3 = expf(v3-mx);
        float sum = e0+e1+e2+e3;
        #pragma unroll
        for (int off = 16; off; off >>= 1)
            sum += __shfl_xor_sync(0xffffffffu, sum, off);
        float inv = 1.f/sum;
        float* dst = g_attn + (b*SEQ + jt + r)*SEQ;
        dst[lane     ] = e0*inv;
        dst[lane + 32] = e1*inv;
        dst[lane + 64] = e2*inv;
        dst[lane + 96] = e3*inv;
    }
}

// ---------------- kernel C: pairwise MLP GEMM -> g_lie  (FFMA2) ------------
__global__ void __launch_bounds__(256, 2)
pair_kernel(const float* __restrict__ b1, const float* __restrict__ W2,
            const float* __restrict__ b2)
{
    __shared__ __align__(16) float Ujb[256];
    __shared__ __align__(16) float As[32*132];   // [kk][i]
    __shared__ __align__(16) float Bs[32*132];   // [kk][c]

    int row = blockIdx.x;          // b*128 + j
    int b   = row >> 7;
    int t   = threadIdx.x;

    Ujb[t] = g_U[row*256 + t] + b1[t];

    int i0 = (t & 15) * 8;
    int c0 = (t >> 4) * 8;

    unsigned bsBase = (unsigned)__cvta_generic_to_shared(Bs) + c0*4;

    u64 acc2[8][4];
    #pragma unroll
    for (int i = 0; i < 8; i++)
        #pragma unroll
        for (int j = 0; j < 4; j++) acc2[i][j] = 0ull;

    for (int k0 = 0; k0 < 256; k0 += 32) {
        __syncthreads();
        #pragma unroll
        for (int s = 0; s < 16; s++) {
            int idx = t + 256*s;          // 4096
            int i = idx >> 5, kk = idx & 31;
            float u = g_U[(b*SEQ + i)*256 + k0 + kk];
            As[kk*132 + i] = ftanh(Ujb[k0 + kk] - u);
        }
        #pragma unroll
        for (int s = 0; s < 15; s++) {
            int idx = t + 256*s;          // 3840
            int c = idx >> 5, kk = idx & 31;
            Bs[kk*132 + c] = W2[c*256 + k0 + kk];
        }
        { int c = 120 + (t >> 5), kk = t & 31; Bs[kk*132 + c] = 0.f; }
        __syncthreads();

        #pragma unroll
        for (int kk = 0; kk < 32; kk++) {
            unsigned bAddr = bsBase + kk*132*4;
            float4 aA = *(const float4*)&As[kk*132 + i0];
            float4 aB = *(const float4*)&As[kk*132 + i0 + 4];
            u64 b01, b23, b45, b67;
            LDS_2x64(b01, b23, bAddr);
            LDS_2x64(b45, b67, bAddr + 16);
            float av[8] = {aA.x,aA.y,aA.z,aA.w,aB.x,aB.y,aB.z,aB.w};
            #pragma unroll
            for (int i = 0; i < 8; i++) {
                u64 ad; DUP2(ad, av[i]);
                FMA2(acc2[i][0], ad, b01, acc2[i][0]);
                FMA2(acc2[i][1], ad, b23, acc2[i][1]);
                FMA2(acc2[i][2], ad, b45, acc2[i][2]);
                FMA2(acc2[i][3], ad, b67, acc2[i][3]);
            }
        }
    }

    if (c0 < SO) {
        float4 bb0 = *(const float4*)&b2[c0];
        float4 bb1 = *(const float4*)&b2[c0 + 4];
        float bb[8] = {bb0.x,bb0.y,bb0.z,bb0.w,bb1.x,bb1.y,bb1.z,bb1.w};
        #pragma unroll
        for (int ii = 0; ii < 8; ii++) {
            float v[8];
            #pragma unroll
            for (int jp = 0; jp < 4; jp++) {
                unsigned lo, hi;
                UNPK2(lo, hi, acc2[ii][jp]);
                v[2*jp]   = __uint_as_float(lo) + bb[2*jp];
                v[2*jp+1] = __uint_as_float(hi) + bb[2*jp+1];
            }
            size_t p = (size_t)row*SEQ + (i0 + ii);
            float* dst = g_lie + p*SO + c0;
            *(float4*)dst     = make_float4(v[0],v[1],v[2],v[3]);
            *(float4*)(dst+4) = make_float4(v[4],v[5],v[6],v[7]);
        }
    }
}

// ---------------- tf32 3x-split MMA helpers --------------------------------
__device__ __forceinline__ unsigned f2tf(float x) {
    unsigned r; asm("cvt.rna.tf32.f32 %0, %1;" : "=r"(r) : "f"(x)); return r;
}

__device__ __forceinline__ void mma8(float* d, const unsigned* a, const unsigned* b) {
    asm("mma.sync.aligned.m16n8k8.row.col.f32.tf32.tf32.f32 "
        "{%0,%1,%2,%3}, {%4,%5,%6,%7}, {%8,%9}, {%0,%1,%2,%3};"
        : "+f"(d[0]), "+f"(d[1]), "+f"(d[2]), "+f"(d[3])
        : "r"(a[0]), "r"(a[1]), "r"(a[2]), "r"(a[3]), "r"(b[0]), "r"(b[1]));
}

// A-fragment of 16x16 matrix M (row-major stride 20), split hi/lo. [s=kstep][reg]
struct AFrag { unsigned h[2][4]; unsigned l[2][4]; };

__device__ __forceinline__ void load_af(const float* M, int g, int t, AFrag& f) {
    #pragma unroll
    for (int s = 0; s < 2; s++) {
        float v[4];
        v[0] = M[(g  )*20 + t     + 8*s];
        v[1] = M[(g+8)*20 + t     + 8*s];
        v[2] = M[(g  )*20 + t + 4 + 8*s];
        v[3] = M[(g+8)*20 + t + 4 + 8*s];
        #pragma unroll
        for (int q = 0; q < 4; q++) {
            unsigned h = f2tf(v[q]);
            f.h[s][q] = h;
            f.l[s][q] = f2tf(v[q] - __uint_as_float(h));
        }
    }
}

// D[2][4] += Afrag * Y (Y in smem row-major stride 20), 3xTF32 per sub-mma.
__device__ __forceinline__ void mm16(float D[2][4], const AFrag& a,
                                     const float* Y, int g, int t) {
    #pragma unroll
    for (int j = 0; j < 2; j++)
        #pragma unroll
        for (int s = 0; s < 2; s++) {
            float v0 = Y[(t     + 8*s)*20 + g + 8*j];
            float v1 = Y[(t + 4 + 8*s)*20 + g + 8*j];
            unsigned bh[2], bl[2];
            bh[0] = f2tf(v0); bh[1] = f2tf(v1);
            bl[0] = f2tf(v0 - __uint_as_float(bh[0]));
            bl[1] = f2tf(v1 - __uint_as_float(bh[1]));
            mma8(D[j], a.h[s], bl);
            mma8(D[j], a.l[s], bh);
            mma8(D[j], a.h[s], bh);
        }
}

// store C-layout regs -> row-major stride-20 smem
__device__ __forceinline__ void st_cr(float* M, const float D[2][4], int g, int t) {
    *(float2*)&M[(g  )*20 + 2*t    ] = make_float2(D[0][0], D[0][1]);
    *(float2*)&M[(g  )*20 + 2*t + 8] = make_float2(D[1][0], D[1][1]);
    *(float2*)&M[(g+8)*20 + 2*t    ] = make_float2(D[0][2], D[0][3]);
    *(float2*)&M[(g+8)*20 + 2*t + 8] = make_float2(D[1][2], D[1][3]);
}

// ---------------- kernel D: expm via 3xTF32 tensor-core matmuls ------------
#define EXPM_BLOCKS 1024
#define NPAIRS (NB*SEQ*SEQ)      // 65536

__global__ void __launch_bounds__(128)
expm_kernel(const float* __restrict__ xm_g, float* __restrict__ Tout)
{
    __shared__ __align__(16) float mm[4*4*320];   // 4 warps x (A,A2,A3,T) x 320
    int tid = threadIdx.x, lane = tid & 31, w = tid >> 5;
    float* Ab  = mm + w*1280;
    float* A2b = Ab + 320;
    float* A3b = Ab + 640;
    float* Tb  = Ab + 960;

    int g = lane >> 2;       // row group 0..7 (rows g, g+8)
    int t = lane & 3;        // col group (cols 2t,2t+1 / k-cols t,t+4)

    const float c3=1.f/6.f, c4=1.f/24.f, c5=1.f/120.f;
    const float c6=1.f/720.f, c7=1.f/5040.f, c8=1.f/40320.f, c9=1.f/362880.f;

    // diagonal indicator per C-layout register
    float dg[2][4];
    #pragma unroll
    for (int j = 0; j < 2; j++)
        #pragma unroll
        for (int q = 0; q < 4; q++)
            dg[j][q] = ((g + 8*(q>>1)) == (2*t + (q&1) + 8*j)) ? 1.f : 0.f;

    for (int p = blockIdx.x*4 + w; p < NPAIRS; p += EXPM_BLOCKS*4) {
        int row = p >> 7;
        int i   = p & 127;
        int b   = row >> 7;

        // ---- scatter lie -> skew A ----
        const float* lr = g_lie + (size_t)p*SO;
        if (lane < 16) Ab[lane*20 + lane] = 0.f;
        #pragma unroll
        for (int q = 0; q < 4; q++) {
            int l = lane + 32*q;
            if (l < SO) {
                float v = lr[l];
                int rI = c_tri_r[l], cI = c_tri_c[l];
                Ab[rI*20 + cI] =  v;
                Ab[cI*20 + rI] = -v;
            }
        }
        __syncwarp();

        // ---- load A C-layout, norm, scale ----
        float Acr[2][4];
        {
            float2 v;
            v = *(float2*)&Ab[(g  )*20 + 2*t    ]; Acr[0][0]=v.x; Acr[0][1]=v.y;
            v = *(float2*)&Ab[(g  )*20 + 2*t + 8]; Acr[1][0]=v.x; Acr[1][1]=v.y;
            v = *(float2*)&Ab[(g+8)*20 + 2*t    ]; Acr[0][2]=v.x; Acr[0][3]=v.y;
            v = *(float2*)&Ab[(g+8)*20 + 2*t + 8]; Acr[1][2]=v.x; Acr[1][3]=v.y;
        }
        float rs0 = fabsf(Acr[0][0])+fabsf(Acr[0][1])+fabsf(Acr[1][0])+fabsf(Acr[1][1]);
        float rs1 = fabsf(Acr[0][2])+fabsf(Acr[0][3])+fabsf(Acr[1][2])+fabsf(Acr[1][3]);
        #pragma unroll
        for (int off = 1; off <= 2; off <<= 1) {
            rs0 += __shfl_xor_sync(0xffffffffu, rs0, off);
            rs1 += __shfl_xor_sync(0xffffffffu, rs1, off);
        }
        float mx = fmaxf(rs0, rs1);
        #pragma unroll
        for (int off = 4; off <= 16; off <<= 1)
            mx = fmaxf(mx, __shfl_xor_sync(0xffffffffu, mx, off));
        int sct = 0;
        if (mx > 1.f) { sct = (int)ceilf(log2f(mx)); if (sct > 12) sct = 12; }
        float scale = __uint_as_float((uint32_t)(127 - sct) << 23);
        #pragma unroll
        for (int j = 0; j < 2; j++)
            #pragma unroll
            for (int q = 0; q < 4; q++) Acr[j][q] *= scale;
        st_cr(Ab, Acr, g, t);
        __syncwarp();

        // ---- A2 = A*A ----
        AFrag fA;
        load_af(Ab, g, t, fA);
        float A2cr[2][4] = {{0.f,0.f,0.f,0.f},{0.f,0.f,0.f,0.f}};
        mm16(A2cr, fA, Ab, g, t);
        st_cr(A2b, A2cr, g, t);
        __syncwarp();

        // ---- A3 = A*A2 (A-frag reuse) ----
        float A3cr[2][4] = {{0.f,0.f,0.f,0.f},{0.f,0.f,0.f,0.f}};
        mm16(A3cr, fA, A2b, g, t);

        // ---- B2 = c6 I + c7 A + c8 A2 + c9 A3 -> Tb; store A3 -> A3b ----
        {
            float E[2][4];
            #pragma unroll
            for (int j = 0; j < 2; j++)
                #pragma unroll
                for (int q = 0; q < 4; q++)
                    E[j][q] = fmaf(c6, dg[j][q],
                              fmaf(c7, Acr[j][q],
                              fmaf(c8, A2cr[j][q], c9 * A3cr[j][q])));
            st_cr(Tb, E, g, t);
        }
        st_cr(A3b, A3cr, g, t);
        __syncwarp();

        // ---- M = A3*B2 + (c3 I + c4 A + c5 A2) ----
        AFrag f3;
        load_af(A3b, g, t, f3);
        float R[2][4];
        #pragma unroll
        for (int j = 0; j < 2; j++)
            #pragma unroll
            for (int q = 0; q < 4; q++)
                R[j][q] = fmaf(c3, dg[j][q],
                          fmaf(c4, Acr[j][q], c5 * A2cr[j][q]));
        mm16(R, f3, Tb, g, t);
        __syncwarp();                 // all lanes done reading Tb (B2)
        st_cr(Tb, R, g, t);
        __syncwarp();

        // ---- R = A3*M + (I + A + A2/2) ----
        #pragma unroll
        for (int j = 0; j < 2; j++)
            #pragma unroll
            for (int q = 0; q < 4; q++)
                R[j][q] = fmaf(0.5f, A2cr[j][q], Acr[j][q]) + dg[j][q];
        mm16(R, f3, Tb, g, t);

        // ---- squarings ----
        for (int q = 0; q < sct; q++) {
            __syncwarp();
            st_cr(Tb, R, g, t);
            __syncwarp();
            AFrag fR;
            load_af(Tb, g, t, fR);
            float R2[2][4] = {{0.f,0.f,0.f,0.f},{0.f,0.f,0.f,0.f}};
            mm16(R2, fR, Tb, g, t);
            #pragma unroll
            for (int j = 0; j < 2; j++)
                #pragma unroll
                for (int qq = 0; qq < 4; qq++) R[j][qq] = R2[j][qq];
        }

        // ---- write T_all ----
        float* dst = Tout + (size_t)p*256;
        *(float2*)&dst[(g  )*16 + 2*t    ] = make_float2(R[0][0], R[0][1]);
        *(float2*)&dst[(g  )*16 + 2*t + 8] = make_float2(R[1][0], R[1][1]);
        *(float2*)&dst[(g+8)*16 + 2*t    ] = make_float2(R[0][2], R[0][3]);
        *(float2*)&dst[(g+8)*16 + 2*t + 8] = make_float2(R[1][2], R[1][3]);

        // ---- transported & settled ----
        const float* xv = xm_g + ((size_t)b*SEQ + i)*DM;
        float x0 = xv[2*t], x1 = xv[2*t+1], x2 = xv[2*t+8], x3 = xv[2*t+9];
        float pg  = R[0][0]*x0 + R[0][1]*x1 + R[1][0]*x2 + R[1][1]*x3;
        float pg8 = R[0][2]*x0 + R[0][3]*x1 + R[1][2]*x2 + R[1][3]*x3;
        #pragma unroll
        for (int off = 1; off <= 2; off <<= 1) {
            pg  += __shfl_xor_sync(0xffffffffu, pg,  off);
            pg8 += __shfl_xor_sync(0xffffffffu, pg8, off);
        }
        if (t == 0) {
            float wgt = g_attn[row*SEQ + i];
            atomicAdd(&g_settled[row*DM + g    ], wgt * pg);
            atomicAdd(&g_settled[row*DM + g + 8], wgt * pg8);
        }
        __syncwarp();
    }
}

// ---------------- kernel E: out projection ---------------------------------
__global__ void __launch_bounds__(256)
out_kernel(const float* __restrict__ Wo, const float* __restrict__ bo,
           float* __restrict__ out)
{
    int gid = blockIdx.x*256 + threadIdx.x;    // 8192
    int row = gid >> 4, d = gid & 15;
    float acc = bo[d];
    #pragma unroll
    for (int e = 0; e < DM; e++)
        acc = fmaf(Wo[d*DM + e], g_settled[row*DM + e], acc);
    out[gid] = acc;
}

// ---------------- launch ----------------------------------------------------
extern "C" void kernel_launch(void* const* d_in, const int* in_sizes, int n_in,
                              void* d_out, int out_size)
{
    const float* xl  = (const float*)d_in[0];
    const float* xmm = (const float*)d_in[1];
    const float* Wq  = (const float*)d_in[2];
    const float* bq  = (const float*)d_in[3];
    const float* Wk  = (const float*)d_in[4];
    const float* bk  = (const float*)d_in[5];
    const float* W1  = (const float*)d_in[6];
    const float* b1  = (const float*)d_in[7];
    const float* W2  = (const float*)d_in[8];
    const float* b2  = (const float*)d_in[9];
    const float* Wo  = (const float*)d_in[10];
    const float* bo  = (const float*)d_in[11];

    float* out  = (float*)d_out;
    float* Tout = out + NB*SEQ*DM;      // T_all follows out

    static bool attr_set = false;
    if (!attr_set) {
        cudaFuncSetAttribute(attn_kernel, cudaFuncAttributeMaxDynamicSharedMemorySize, AT_BYTES);
        attr_set = true;
    }

    prep_kernel<<<dim3(8,8), 256>>>(xl, Wq, bq, Wk, bk, W1);
    attn_kernel<<<16, 256, AT_BYTES>>>();
    pair_kernel<<<ROWS, 256>>>(b1, W2, b2);
    expm_kernel<<<EXPM_BLOCKS, 128>>>(xmm, Tout);
    out_kernel<<<32, 256>>>(Wo, bo, out);
}

// round 10
// speedup vs baseline: 1.4775x; 1.1183x over previous
#include <cuda_runtime.h>
#include <math.h>
#include <stdint.h>

#define NB 4
#define SEQ 128
#define DL 128
#define DM 16
#define SO 120
#define ROWS (NB*SEQ)        // 512

// ---------------- scratch ----------------------------------------------------
__device__ float g_Q[ROWS*DL];
__device__ float g_K[ROWS*DL];
__device__ float g_U[ROWS*256];
__device__ float g_attn[NB*SEQ*SEQ];
__device__ float g_lie[(size_t)NB*SEQ*SEQ*SO];   // 31.5 MB
__device__ float g_settled[ROWS*DM];
__device__ float g_W2h[256*128];                 // W2^T tf32 hi, [k][c]
__device__ float g_W2l[256*128];                 // W2^T tf32 lo, [k][c]

__constant__ int c_tri_r[120] = {
 0,0,0,0,0,0,0,0,0,0,0,0,0,0,0,
 1,1,1,1,1,1,1,1,1,1,1,1,1,1,
 2,2,2,2,2,2,2,2,2,2,2,2,2,
 3,3,3,3,3,3,3,3,3,3,3,3,
 4,4,4,4,4,4,4,4,4,4,4,
 5,5,5,5,5,5,5,5,5,5,
 6,6,6,6,6,6,6,6,6,
 7,7,7,7,7,7,7,7,
 8,8,8,8,8,8,8,
 9,9,9,9,9,9,
 10,10,10,10,10,
 11,11,11,11,
 12,12,12,
 13,13,
 14};
__constant__ int c_tri_c[120] = {
 1,2,3,4,5,6,7,8,9,10,11,12,13,14,15,
 2,3,4,5,6,7,8,9,10,11,12,13,14,15,
 3,4,5,6,7,8,9,10,11,12,13,14,15,
 4,5,6,7,8,9,10,11,12,13,14,15,
 5,6,7,8,9,10,11,12,13,14,15,
 6,7,8,9,10,11,12,13,14,15,
 7,8,9,10,11,12,13,14,15,
 8,9,10,11,12,13,14,15,
 9,10,11,12,13,14,15,
 10,11,12,13,14,15,
 11,12,13,14,15,
 12,13,14,15,
 13,14,15,
 14,15,
 15};

__device__ __forceinline__ float ftanh(float x) {
    float y;
    asm("tanh.approx.f32 %0, %1;" : "=f"(y) : "f"(x));
    return y;
}

__device__ __forceinline__ unsigned f2tf(float x) {
    unsigned r; asm("cvt.rna.tf32.f32 %0, %1;" : "=r"(r) : "f"(x)); return r;
}

__device__ __forceinline__ void mma8(float* d, const unsigned* a, const unsigned* b) {
    asm("mma.sync.aligned.m16n8k8.row.col.f32.tf32.tf32.f32 "
        "{%0,%1,%2,%3}, {%4,%5,%6,%7}, {%8,%9}, {%0,%1,%2,%3};"
        : "+f"(d[0]), "+f"(d[1]), "+f"(d[2]), "+f"(d[3])
        : "r"(a[0]), "r"(a[1]), "r"(a[2]), "r"(a[3]), "r"(b[0]), "r"(b[1]));
}

// ---------------- kernel A: tiled GEMM  C[512 x 512] = X @ [Wq;Wk;W1]^T ----
__global__ void __launch_bounds__(256)
prep_kernel(const float* __restrict__ xl,
            const float* __restrict__ Wq, const float* __restrict__ bq,
            const float* __restrict__ Wk, const float* __restrict__ bk,
            const float* __restrict__ W1)
{
    __shared__ __align__(16) float Xs[64*64];
    __shared__ __align__(16) float Wt[64*68];

    int bx = blockIdx.x, by = blockIdx.y;
    int t  = threadIdx.x;
    int tx = t & 15, ty = t >> 4;

    const float* src;
    if      (by < 2) src = Wq + (by    )*64*DL;
    else if (by < 4) src = Wk + (by - 2)*64*DL;
    else             src = W1 + (by - 4)*64*DL;

    float acc[4][4];
    #pragma unroll
    for (int i = 0; i < 4; i++)
        #pragma unroll
        for (int j = 0; j < 4; j++) acc[i][j] = 0.f;

    for (int k0 = 0; k0 < DL; k0 += 64) {
        __syncthreads();
        #pragma unroll
        for (int s = 0; s < 16; s++) {
            int idx = t + 256*s;
            int r = idx >> 6, k = idx & 63;
            Xs[r*64 + k] = xl[(bx*64 + r)*DL + k0 + k];
            Wt[k*68 + r] = src[r*DL + k0 + k];
        }
        __syncthreads();

        #pragma unroll 8
        for (int k = 0; k < 64; k++) {
            float4 bv = *(const float4*)&Wt[k*68 + tx*4];
            #pragma unroll
            for (int i = 0; i < 4; i++) {
                float a = Xs[(ty*4 + i)*64 + k];
                acc[i][0] = fmaf(a, bv.x, acc[i][0]);
                acc[i][1] = fmaf(a, bv.y, acc[i][1]);
                acc[i][2] = fmaf(a, bv.z, acc[i][2]);
                acc[i][3] = fmaf(a, bv.w, acc[i][3]);
            }
        }
    }

    #pragma unroll
    for (int i = 0; i < 4; i++) {
        int rowg = bx*64 + ty*4 + i;
        int c0   = tx*4;
        if (by < 2) {
            int col = by*64 + c0;
            *(float4*)&g_Q[rowg*DL + col] =
                make_float4(acc[i][0]+bq[col], acc[i][1]+bq[col+1],
                            acc[i][2]+bq[col+2], acc[i][3]+bq[col+3]);
        } else if (by < 4) {
            int col = (by-2)*64 + c0;
            *(float4*)&g_K[rowg*DL + col] =
                make_float4(acc[i][0]+bk[col], acc[i][1]+bk[col+1],
                            acc[i][2]+bk[col+2], acc[i][3]+bk[col+3]);
        } else {
            int col = (by-4)*64 + c0;
            *(float4*)&g_U[rowg*256 + col] =
                make_float4(acc[i][0], acc[i][1], acc[i][2], acc[i][3]);
        }
    }
}

// ---------------- kernel A2: split W2^T into tf32 hi/lo, [k][c] layout -----
__global__ void __launch_bounds__(256)
w2split_kernel(const float* __restrict__ W2)
{
    int idx = blockIdx.x*256 + threadIdx.x;   // 32768 = 256 k x 128 c
    int k = idx >> 7, c = idx & 127;
    float v = (c < SO) ? W2[c*256 + k] : 0.f;
    unsigned h = f2tf(v);
    g_W2h[idx] = __uint_as_float(h);
    g_W2l[idx] = __uint_as_float(f2tf(v - __uint_as_float(h)));
}

// ---------------- kernel B: attention softmax (+ zero g_settled) -----------
#define AT_QS 0
#define AT_KT (AT_QS + 32*128)
#define AT_S  (AT_KT + 128*132)
#define AT_FLOATS (AT_S + 32*132)
#define AT_BYTES  (AT_FLOATS*4)

__global__ void __launch_bounds__(256)
attn_kernel()
{
    extern __shared__ float sm[];
    float* Qs = sm + AT_QS;
    float* Kt = sm + AT_KT;
    float* S  = sm + AT_S;

    int b  = blockIdx.x >> 2;
    int jt = (blockIdx.x & 3) * 32;
    int t  = threadIdx.x;
    int tx = t & 15, ty = t >> 4;

    for (int z = t; z < 512; z += 256) g_settled[blockIdx.x*512 + z] = 0.f;

    for (int idx = t; idx < 32*128; idx += 256) {
        int j = idx >> 7, k = idx & 127;
        Qs[j*128 + k] = g_Q[(b*SEQ + jt + j)*DL + k];
    }
    for (int idx = t; idx < 128*128; idx += 256) {
        int i = idx >> 7, k = idx & 127;
        Kt[k*132 + i] = g_K[(b*SEQ + i)*DL + k];
    }
    __syncthreads();

    float acc[2][8];
    #pragma unroll
    for (int i = 0; i < 2; i++)
        #pragma unroll
        for (int j = 0; j < 8; j++) acc[i][j] = 0.f;

    int j0 = ty*2, i0 = tx*8;
    #pragma unroll 4
    for (int k = 0; k < 128; k++) {
        float q0 = Qs[(j0  )*128 + k];
        float q1 = Qs[(j0+1)*128 + k];
        float4 k0v = *(const float4*)&Kt[k*132 + i0];
        float4 k1v = *(const float4*)&Kt[k*132 + i0 + 4];
        acc[0][0]=fmaf(q0,k0v.x,acc[0][0]); acc[0][1]=fmaf(q0,k0v.y,acc[0][1]);
        acc[0][2]=fmaf(q0,k0v.z,acc[0][2]); acc[0][3]=fmaf(q0,k0v.w,acc[0][3]);
        acc[0][4]=fmaf(q0,k1v.x,acc[0][4]); acc[0][5]=fmaf(q0,k1v.y,acc[0][5]);
        acc[0][6]=fmaf(q0,k1v.z,acc[0][6]); acc[0][7]=fmaf(q0,k1v.w,acc[0][7]);
        acc[1][0]=fmaf(q1,k0v.x,acc[1][0]); acc[1][1]=fmaf(q1,k0v.y,acc[1][1]);
        acc[1][2]=fmaf(q1,k0v.z,acc[1][2]); acc[1][3]=fmaf(q1,k0v.w,acc[1][3]);
        acc[1][4]=fmaf(q1,k1v.x,acc[1][4]); acc[1][5]=fmaf(q1,k1v.y,acc[1][5]);
        acc[1][6]=fmaf(q1,k1v.z,acc[1][6]); acc[1][7]=fmaf(q1,k1v.w,acc[1][7]);
    }
    const float sc = 0.08838834764831845f;
    #pragma unroll
    for (int i = 0; i < 2; i++) {
        *(float4*)&S[(j0+i)*132 + i0] =
            make_float4(acc[i][0]*sc, acc[i][1]*sc, acc[i][2]*sc, acc[i][3]*sc);
        *(float4*)&S[(j0+i)*132 + i0 + 4] =
            make_float4(acc[i][4]*sc, acc[i][5]*sc, acc[i][6]*sc, acc[i][7]*sc);
    }
    __syncthreads();

    int w = t >> 5, lane = t & 31;
    for (int q = 0; q < 4; q++) {
        int r = w*4 + q;
        float v0 = S[r*132 + lane      ];
        float v1 = S[r*132 + lane + 32 ];
        float v2 = S[r*132 + lane + 64 ];
        float v3 = S[r*132 + lane + 96 ];
        float mx = fmaxf(fmaxf(v0,v1), fmaxf(v2,v3));
        #pragma unroll
        for (int off = 16; off; off >>= 1)
            mx = fmaxf(mx, __shfl_xor_sync(0xffffffffu, mx, off));
        float e0 = expf(v0-mx), e1 = expf(v1-mx), e2 = expf(v2-mx), e3 = expf(v3-mx);
        float sum = e0+e1+e2+e3;
        #pragma unroll
        for (int off = 16; off; off >>= 1)
            sum += __shfl_xor_sync(0xffffffffu, sum, off);
        float inv = 1.f/sum;
        float* dst = g_attn + (b*SEQ + jt + r)*SEQ;
        dst[lane     ] = e0*inv;
        dst[lane + 32] = e1*inv;
        dst[lane + 64] = e2*inv;
        dst[lane + 96] = e3*inv;
    }
}

// ---------------- kernel C: pairwise MLP GEMM via 3xTF32 MMA ---------------
// Block = (b,j): C[128 i x 120 c] = tanh(Ujb - U_i) @ W2^T.
// 8 warps; warp w owns i-rows [16w,16w+16), all 120 cols (15 n-tiles of 8).
// smem floats: Ujb[256] | b2s[128] | Hs[128*36] | Bh[32*136] | Bl[32*136]
#define PK_UJB 0
#define PK_B2  (PK_UJB + 256)
#define PK_H   (PK_B2 + 128)
#define PK_BH  (PK_H + 128*36)
#define PK_BL  (PK_BH + 32*136)
#define PK_FLOATS (PK_BL + 32*136)
#define PK_BYTES  (PK_FLOATS*4)

__global__ void __launch_bounds__(256, 2)
pair_kernel(const float* __restrict__ b1, const float* __restrict__ b2)
{
    extern __shared__ float psm[];
    float* Ujb = psm + PK_UJB;
    float* b2s = psm + PK_B2;
    float* Hs  = psm + PK_H;
    float* Bh  = psm + PK_BH;
    float* Bl  = psm + PK_BL;

    int row = blockIdx.x;          // b*128 + j
    int b   = row >> 7;
    int t   = threadIdx.x;
    int lane = t & 31, w = t >> 5;
    int g = lane >> 2, tt = lane & 3;
    int ibase = w * 16;

    Ujb[t] = g_U[row*256 + t] + b1[t];
    if (t < 128) b2s[t] = (t < SO) ? b2[t] : 0.f;

    float acc[15][4];
    #pragma unroll
    for (int n = 0; n < 15; n++)
        #pragma unroll
        for (int q = 0; q < 4; q++) acc[n][q] = 0.f;

    for (int k0 = 0; k0 < 256; k0 += 32) {
        __syncthreads();
        #pragma unroll
        for (int s = 0; s < 16; s++) {
            int idx = t + 256*s;                // 4096
            {   int i = idx >> 5, k = idx & 31;
                Hs[i*36 + k] = ftanh(Ujb[k0 + k] - g_U[(b*SEQ + i)*256 + k0 + k]); }
            {   int k = idx >> 7, c = idx & 127;
                Bh[k*136 + c] = g_W2h[(k0 + k)*128 + c];
                Bl[k*136 + c] = g_W2l[(k0 + k)*128 + c]; }
        }
        __syncthreads();

        #pragma unroll
        for (int s = 0; s < 4; s++) {
            float v0 = Hs[(ibase+g  )*36 + 8*s + tt];
            float v1 = Hs[(ibase+g+8)*36 + 8*s + tt];
            float v2 = Hs[(ibase+g  )*36 + 8*s + tt + 4];
            float v3 = Hs[(ibase+g+8)*36 + 8*s + tt + 4];
            unsigned ah[4], al[4];
            ah[0]=f2tf(v0); al[0]=f2tf(v0-__uint_as_float(ah[0]));
            ah[1]=f2tf(v1); al[1]=f2tf(v1-__uint_as_float(ah[1]));
            ah[2]=f2tf(v2); al[2]=f2tf(v2-__uint_as_float(ah[2]));
            ah[3]=f2tf(v3); al[3]=f2tf(v3-__uint_as_float(ah[3]));
            int kr0 = (8*s + tt    )*136 + g;
            int kr1 = (8*s + tt + 4)*136 + g;
            #pragma unroll
            for (int n = 0; n < 15; n++) {
                unsigned bh[2], bl_[2];
                bh[0]  = __float_as_uint(Bh[kr0 + 8*n]);
                bh[1]  = __float_as_uint(Bh[kr1 + 8*n]);
                bl_[0] = __float_as_uint(Bl[kr0 + 8*n]);
                bl_[1] = __float_as_uint(Bl[kr1 + 8*n]);
                mma8(acc[n], ah, bl_);
                mma8(acc[n], al, bh);
                mma8(acc[n], ah, bh);
            }
        }
    }

    // epilogue: bias + store
    size_t p0 = (size_t)row*SEQ + ibase + g;
    size_t p1 = p0 + 8;
    #pragma unroll
    for (int n = 0; n < 15; n++) {
        int c = 8*n + 2*tt;
        float bb0 = b2s[c], bb1 = b2s[c+1];
        *(float2*)&g_lie[p0*SO + c] = make_float2(acc[n][0] + bb0, acc[n][1] + bb1);
        *(float2*)&g_lie[p1*SO + c] = make_float2(acc[n][2] + bb0, acc[n][3] + bb1);
    }
}

// ---------------- tf32 3x-split MMA helpers for expm -----------------------
// A-fragment of 16x16 matrix M (row-major stride 20), split hi/lo. [s=kstep][reg]
struct AFrag { unsigned h[2][4]; unsigned l[2][4]; };

__device__ __forceinline__ void load_af(const float* M, int g, int t, AFrag& f) {
    #pragma unroll
    for (int s = 0; s < 2; s++) {
        float v[4];
        v[0] = M[(g  )*20 + t     + 8*s];
        v[1] = M[(g+8)*20 + t     + 8*s];
        v[2] = M[(g  )*20 + t + 4 + 8*s];
        v[3] = M[(g+8)*20 + t + 4 + 8*s];
        #pragma unroll
        for (int q = 0; q < 4; q++) {
            unsigned h = f2tf(v[q]);
            f.h[s][q] = h;
            f.l[s][q] = f2tf(v[q] - __uint_as_float(h));
        }
    }
}

// D[2][4] += Afrag * Y (Y in smem row-major stride 20), 3xTF32 per sub-mma.
__device__ __forceinline__ void mm16(float D[2][4], const AFrag& a,
                                     const float* Y, int g, int t) {
    #pragma unroll
    for (int j = 0; j < 2; j++)
        #pragma unroll
        for (int s = 0; s < 2; s++) {
            float v0 = Y[(t     + 8*s)*20 + g + 8*j];
            float v1 = Y[(t + 4 + 8*s)*20 + g + 8*j];
            unsigned bh[2], bl[2];
            bh[0] = f2tf(v0); bh[1] = f2tf(v1);
            bl[0] = f2tf(v0 - __uint_as_float(bh[0]));
            bl[1] = f2tf(v1 - __uint_as_float(bh[1]));
            mma8(D[j], a.h[s], bl);
            mma8(D[j], a.l[s], bh);
            mma8(D[j], a.h[s], bh);
        }
}

// store C-layout regs -> row-major stride-20 smem
__device__ __forceinline__ void st_cr(float* M, const float D[2][4], int g, int t) {
    *(float2*)&M[(g  )*20 + 2*t    ] = make_float2(D[0][0], D[0][1]);
    *(float2*)&M[(g  )*20 + 2*t + 8] = make_float2(D[1][0], D[1][1]);
    *(float2*)&M[(g+8)*20 + 2*t    ] = make_float2(D[0][2], D[0][3]);
    *(float2*)&M[(g+8)*20 + 2*t + 8] = make_float2(D[1][2], D[1][3]);
}

// ---------------- kernel D: expm via 3xTF32 tensor-core matmuls ------------
#define EXPM_BLOCKS 1024
#define NPAIRS (NB*SEQ*SEQ)      // 65536

__global__ void __launch_bounds__(128)
expm_kernel(const float* __restrict__ xm_g, float* __restrict__ Tout)
{
    __shared__ __align__(16) float mm[4*4*320];   // 4 warps x (A,A2,A3,T) x 320
    int tid = threadIdx.x, lane = tid & 31, w = tid >> 5;
    float* Ab  = mm + w*1280;
    float* A2b = Ab + 320;
    float* A3b = Ab + 640;
    float* Tb  = Ab + 960;

    int g = lane >> 2;       // row group 0..7 (rows g, g+8)
    int t = lane & 3;        // col group

    const float c3=1.f/6.f, c4=1.f/24.f, c5=1.f/120.f;
    const float c6=1.f/720.f, c7=1.f/5040.f, c8=1.f/40320.f, c9=1.f/362880.f;

    float dg[2][4];
    #pragma unroll
    for (int j = 0; j < 2; j++)
        #pragma unroll
        for (int q = 0; q < 4; q++)
            dg[j][q] = ((g + 8*(q>>1)) == (2*t + (q&1) + 8*j)) ? 1.f : 0.f;

    for (int p = blockIdx.x*4 + w; p < NPAIRS; p += EXPM_BLOCKS*4) {
        int row = p >> 7;
        int i   = p & 127;
        int b   = row >> 7;

        // ---- scatter lie -> skew A ----
        const float* lr = g_lie + (size_t)p*SO;
        if (lane < 16) Ab[lane*20 + lane] = 0.f;
        #pragma unroll
        for (int q = 0; q < 4; q++) {
            int l = lane + 32*q;
            if (l < SO) {
                float v = lr[l];
                int rI = c_tri_r[l], cI = c_tri_c[l];
                Ab[rI*20 + cI] =  v;
                Ab[cI*20 + rI] = -v;
            }
        }
        __syncwarp();

        // ---- load A C-layout, norm, scale ----
        float Acr[2][4];
        {
            float2 v;
            v = *(float2*)&Ab[(g  )*20 + 2*t    ]; Acr[0][0]=v.x; Acr[0][1]=v.y;
            v = *(float2*)&Ab[(g  )*20 + 2*t + 8]; Acr[1][0]=v.x; Acr[1][1]=v.y;
            v = *(float2*)&Ab[(g+8)*20 + 2*t    ]; Acr[0][2]=v.x; Acr[0][3]=v.y;
            v = *(float2*)&Ab[(g+8)*20 + 2*t + 8]; Acr[1][2]=v.x; Acr[1][3]=v.y;
        }
        float rs0 = fabsf(Acr[0][0])+fabsf(Acr[0][1])+fabsf(Acr[1][0])+fabsf(Acr[1][1]);
        float rs1 = fabsf(Acr[0][2])+fabsf(Acr[0][3])+fabsf(Acr[1][2])+fabsf(Acr[1][3]);
        #pragma unroll
        for (int off = 1; off <= 2; off <<= 1) {
            rs0 += __shfl_xor_sync(0xffffffffu, rs0, off);
            rs1 += __shfl_xor_sync(0xffffffffu, rs1, off);
        }
        float mx = fmaxf(rs0, rs1);
        #pragma unroll
        for (int off = 4; off <= 16; off <<= 1)
            mx = fmaxf(mx, __shfl_xor_sync(0xffffffffu, mx, off));
        int sct = 0;
        if (mx > 1.f) { sct = (int)ceilf(log2f(mx)); if (sct > 12) sct = 12; }
        float scale = __uint_as_float((uint32_t)(127 - sct) << 23);
        #pragma unroll
        for (int j = 0; j < 2; j++)
            #pragma unroll
            for (int q = 0; q < 4; q++) Acr[j][q] *= scale;
        st_cr(Ab, Acr, g, t);
        __syncwarp();

        // ---- A2 = A*A ----
        AFrag fA;
        load_af(Ab, g, t, fA);
        float A2cr[2][4] = {{0.f,0.f,0.f,0.f},{0.f,0.f,0.f,0.f}};
        mm16(A2cr, fA, Ab, g, t);
        st_cr(A2b, A2cr, g, t);
        __syncwarp();

        // ---- A3 = A*A2 (A-frag reuse) ----
        float A3cr[2][4] = {{0.f,0.f,0.f,0.f},{0.f,0.f,0.f,0.f}};
        mm16(A3cr, fA, A2b, g, t);

        // ---- B2 = c6 I + c7 A + c8 A2 + c9 A3 -> Tb; store A3 -> A3b ----
        {
            float E[2][4];
            #pragma unroll
            for (int j = 0; j < 2; j++)
                #pragma unroll
                for (int q = 0; q < 4; q++)
                    E[j][q] = fmaf(c6, dg[j][q],
                              fmaf(c7, Acr[j][q],
                              fmaf(c8, A2cr[j][q], c9 * A3cr[j][q])));
            st_cr(Tb, E, g, t);
        }
        st_cr(A3b, A3cr, g, t);
        __syncwarp();

        // ---- M = A3*B2 + (c3 I + c4 A + c5 A2) ----
        AFrag f3;
        load_af(A3b, g, t, f3);
        float R[2][4];
        #pragma unroll
        for (int j = 0; j < 2; j++)
            #pragma unroll
            for (int q = 0; q < 4; q++)
                R[j][q] = fmaf(c3, dg[j][q],
                          fmaf(c4, Acr[j][q], c5 * A2cr[j][q]));
        mm16(R, f3, Tb, g, t);
        __syncwarp();
        st_cr(Tb, R, g, t);
        __syncwarp();

        // ---- R = A3*M + (I + A + A2/2) ----
        #pragma unroll
        for (int j = 0; j < 2; j++)
            #pragma unroll
            for (int q = 0; q < 4; q++)
                R[j][q] = fmaf(0.5f, A2cr[j][q], Acr[j][q]) + dg[j][q];
        mm16(R, f3, Tb, g, t);

        // ---- squarings ----
        for (int q = 0; q < sct; q++) {
            __syncwarp();
            st_cr(Tb, R, g, t);
            __syncwarp();
            AFrag fR;
            load_af(Tb, g, t, fR);
            float R2[2][4] = {{0.f,0.f,0.f,0.f},{0.f,0.f,0.f,0.f}};
            mm16(R2, fR, Tb, g, t);
            #pragma unroll
            for (int j = 0; j < 2; j++)
                #pragma unroll
                for (int qq = 0; qq < 4; qq++) R[j][qq] = R2[j][qq];
        }

        // ---- write T_all ----
        float* dst = Tout + (size_t)p*256;
        *(float2*)&dst[(g  )*16 + 2*t    ] = make_float2(R[0][0], R[0][1]);
        *(float2*)&dst[(g  )*16 + 2*t + 8] = make_float2(R[1][0], R[1][1]);
        *(float2*)&dst[(g+8)*16 + 2*t    ] = make_float2(R[0][2], R[0][3]);
        *(float2*)&dst[(g+8)*16 + 2*t + 8] = make_float2(R[1][2], R[1][3]);

        // ---- transported & settled ----
        const float* xv = xm_g + ((size_t)b*SEQ + i)*DM;
        float x0 = xv[2*t], x1 = xv[2*t+1], x2 = xv[2*t+8], x3 = xv[2*t+9];
        float pg  = R[0][0]*x0 + R[0][1]*x1 + R[1][0]*x2 + R[1][1]*x3;
        float pg8 = R[0][2]*x0 + R[0][3]*x1 + R[1][2]*x2 + R[1][3]*x3;
        #pragma unroll
        for (int off = 1; off <= 2; off <<= 1) {
            pg  += __shfl_xor_sync(0xffffffffu, pg,  off);
            pg8 += __shfl_xor_sync(0xffffffffu, pg8, off);
        }
        if (t == 0) {
            float wgt = g_attn[row*SEQ + i];
            atomicAdd(&g_settled[row*DM + g    ], wgt * pg);
            atomicAdd(&g_settled[row*DM + g + 8], wgt * pg8);
        }
        __syncwarp();
    }
}

// ---------------- kernel E: out projection ---------------------------------
__global__ void __launch_bounds__(256)
out_kernel(const float* __restrict__ Wo, const float* __restrict__ bo,
           float* __restrict__ out)
{
    int gid = blockIdx.x*256 + threadIdx.x;    // 8192
    int row = gid >> 4, d = gid & 15;
    float acc = bo[d];
    #pragma unroll
    for (int e = 0; e < DM; e++)
        acc = fmaf(Wo[d*DM + e], g_settled[row*DM + e], acc);
    out[gid] = acc;
}

// ---------------- launch ----------------------------------------------------
extern "C" void kernel_launch(void* const* d_in, const int* in_sizes, int n_in,
                              void* d_out, int out_size)
{
    const float* xl  = (const float*)d_in[0];
    const float* xmm = (const float*)d_in[1];
    const float* Wq  = (const float*)d_in[2];
    const float* bq  = (const float*)d_in[3];
    const float* Wk  = (const float*)d_in[4];
    const float* bk  = (const float*)d_in[5];
    const float* W1  = (const float*)d_in[6];
    const float* b1  = (const float*)d_in[7];
    const float* W2  = (const float*)d_in[8];
    const float* b2  = (const float*)d_in[9];
    const float* Wo  = (const float*)d_in[10];
    const float* bo  = (const float*)d_in[11];

    float* out  = (float*)d_out;
    float* Tout = out + NB*SEQ*DM;      // T_all follows out

    static bool attr_set = false;
    if (!attr_set) {
        cudaFuncSetAttribute(attn_kernel, cudaFuncAttributeMaxDynamicSharedMemorySize, AT_BYTES);
        cudaFuncSetAttribute(pair_kernel, cudaFuncAttributeMaxDynamicSharedMemorySize, PK_BYTES);
        attr_set = true;
    }

    prep_kernel<<<dim3(8,8), 256>>>(xl, Wq, bq, Wk, bk, W1);
    w2split_kernel<<<128, 256>>>(W2);
    attn_kernel<<<16, 256, AT_BYTES>>>();
    pair_kernel<<<ROWS, 256, PK_BYTES>>>(b1, b2);
    expm_kernel<<<EXPM_BLOCKS, 128>>>(xmm, Tout);
    out_kernel<<<32, 256>>>(Wo, bo, out);
}